// round 4
// baseline (speedup 1.0000x reference)
#include <cuda_runtime.h>
#include <math.h>
#include <stdint.h>

#define CB   4
#define CS   2048
#define CD   1024
#define CH   16
#define CDH  64
#define MROWS (CB*CS)
#define LN_EPS 1e-5f

// ---------------- scratch ----------------
__device__ float g_chunk[(size_t)MROWS*CD];
__device__ float g_qkv  [(size_t)MROWS*3*CD];
__device__ float g_attn [(size_t)MROWS*CD];
__device__ float g_proj [(size_t)MROWS*CD];

// ---------------- helpers ----------------
__device__ __forceinline__ uint32_t f2tf(float x) {
    uint32_t u; asm("cvt.rna.tf32.f32 %0, %1;" : "=r"(u) : "f"(x)); return u;
}
__device__ __forceinline__ float tfbits(float x) {
    return __uint_as_float(f2tf(x));
}
__device__ __forceinline__ float ex2f(float x) {
    float y; asm("ex2.approx.f32 %0, %1;" : "=f"(y) : "f"(x)); return y;
}
__device__ __forceinline__ uint32_t pack_bf16(float lo, float hi) {
    uint32_t r; asm("cvt.rn.bf16x2.f32 %0, %1, %2;" : "=r"(r) : "f"(hi), "f"(lo));
    return r;
}
__device__ __forceinline__ void mma_tf32(float c[4], const uint32_t a[4],
                                         const uint32_t b[2]) {
    asm volatile(
        "mma.sync.aligned.m16n8k8.row.col.f32.tf32.tf32.f32 "
        "{%0,%1,%2,%3}, {%4,%5,%6,%7}, {%8,%9}, {%0,%1,%2,%3};\n"
        : "+f"(c[0]), "+f"(c[1]), "+f"(c[2]), "+f"(c[3])
        : "r"(a[0]), "r"(a[1]), "r"(a[2]), "r"(a[3]), "r"(b[0]), "r"(b[1]));
}
__device__ __forceinline__ void mma_bf16(float c[4], const uint32_t a[4],
                                         const uint32_t b[2]) {
    asm volatile(
        "mma.sync.aligned.m16n8k16.row.col.f32.bf16.bf16.f32 "
        "{%0,%1,%2,%3}, {%4,%5,%6,%7}, {%8,%9}, {%0,%1,%2,%3};\n"
        : "+f"(c[0]), "+f"(c[1]), "+f"(c[2]), "+f"(c[3])
        : "r"(a[0]), "r"(a[1]), "r"(a[2]), "r"(a[3]), "r"(b[0]), "r"(b[1]));
}
__device__ __forceinline__ uint32_t smem_u32(const void* p) {
    return (uint32_t)__cvta_generic_to_shared(p);
}
__device__ __forceinline__ void cp16(uint32_t dst, const void* src) {
    asm volatile("cp.async.cg.shared.global [%0], [%1], 16;\n"
                 :: "r"(dst), "l"(src));
}
__device__ __forceinline__ void cp16z(uint32_t dst, const void* src, int srcsz) {
    asm volatile("cp.async.cg.shared.global [%0], [%1], 16, %2;\n"
                 :: "r"(dst), "l"(src), "r"(srcsz));
}
__device__ __forceinline__ void cp_commit() {
    asm volatile("cp.async.commit_group;\n");
}
template<int N> __device__ __forceinline__ void cp_wait() {
    asm volatile("cp.async.wait_group %0;\n" :: "n"(N));
}

// ---------------------------------------------------------------------------
// TF32 NT GEMM, cp.async 3-stage: C = A @ B^T + bias
// 128x128x32 tile, 256 threads, warp tile 64x32.
// tf32 rna conversion done once per stage in smem (not per fragment).
// ---------------------------------------------------------------------------
#define GSTG (128 * 36)
#define GK_SMEM (3 * 2 * GSTG * 4)

template<bool WINDOW>
__global__ __launch_bounds__(256, 2)
void gemm_tf32(const float* __restrict__ A, const float* __restrict__ B,
               const float* __restrict__ bias, float* __restrict__ C,
               int M, int N, int K) {
    extern __shared__ float sm[];
    float* As = sm;              // [3][128][36]
    float* Bs = sm + 3 * GSTG;   // [3][128][36]

    int tid = threadIdx.x;
    int bm = blockIdx.y * 128, bn = blockIdx.x * 128;
    int warp = tid >> 5, lane = tid & 31, gid = lane >> 2, tig = lane & 3;
    int wm = (warp >> 2) * 64, wn = (warp & 3) * 32;

    float acc[4][4][4];
#pragma unroll
    for (int i = 0; i < 4; i++)
#pragma unroll
        for (int j = 0; j < 4; j++)
#pragma unroll
            for (int c = 0; c < 4; c++) acc[i][j][c] = 0.f;

    auto load_stage = [&](int st, int k0) {
#pragma unroll
        for (int p = 0; p < 4; p++) {
            int id  = tid + p * 256;
            int row = id >> 3;
            int kq  = (id & 7) << 2;
            uint32_t da = smem_u32(&As[st * GSTG + row * 36 + kq]);
            if (WINDOW) {
                int m = bm + row;
                int bidx = m >> 11, s = m & (CS - 1);
                int f = k0 + kq, kk = f >> 10, j = f & (CD - 1);
                const float* src = A + (((size_t)bidx * CS + s + kk) << 10) + j;
                cp16z(da, src, (s + kk < CS) ? 16 : 0);
            } else {
                cp16(da, A + (size_t)(bm + row) * K + k0 + kq);
            }
            cp16(smem_u32(&Bs[st * GSTG + row * 36 + kq]),
                 B + (size_t)(bn + row) * K + k0 + kq);
        }
        cp_commit();
    };

    int nk = K >> 5;
    load_stage(0, 0);
    load_stage(1, 32);
    load_stage(2, 64);

    int st = 0;
    for (int kc = 0; kc < nk; kc++) {
        cp_wait<2>();
        // in-place rna tf32 conversion of this thread's own stage elements
#pragma unroll
        for (int p = 0; p < 4; p++) {
            int id  = tid + p * 256;
            int row = id >> 3;
            int kq  = (id & 7) << 2;
            float4* pa = (float4*)&As[st * GSTG + row * 36 + kq];
            float4 va = *pa;
            va.x = tfbits(va.x); va.y = tfbits(va.y);
            va.z = tfbits(va.z); va.w = tfbits(va.w);
            *pa = va;
            float4* pb = (float4*)&Bs[st * GSTG + row * 36 + kq];
            float4 vb = *pb;
            vb.x = tfbits(vb.x); vb.y = tfbits(vb.y);
            vb.z = tfbits(vb.z); vb.w = tfbits(vb.w);
            *pb = vb;
        }
        __syncthreads();
        const float* Ab = As + st * GSTG;
        const float* Bb = Bs + st * GSTG;
#pragma unroll
        for (int g = 0; g < 32; g += 8) {
            uint32_t a[4][4], bf[4][2];
#pragma unroll
            for (int ti = 0; ti < 4; ti++) {
                int m0 = wm + ti * 16 + gid;
                a[ti][0] = __float_as_uint(Ab[m0 * 36 + g + tig]);
                a[ti][1] = __float_as_uint(Ab[(m0 + 8) * 36 + g + tig]);
                a[ti][2] = __float_as_uint(Ab[m0 * 36 + g + tig + 4]);
                a[ti][3] = __float_as_uint(Ab[(m0 + 8) * 36 + g + tig + 4]);
            }
#pragma unroll
            for (int tj = 0; tj < 4; tj++) {
                int n0 = wn + tj * 8 + gid;
                bf[tj][0] = __float_as_uint(Bb[n0 * 36 + g + tig]);
                bf[tj][1] = __float_as_uint(Bb[n0 * 36 + g + tig + 4]);
            }
#pragma unroll
            for (int ti = 0; ti < 4; ti++)
#pragma unroll
                for (int tj = 0; tj < 4; tj++)
                    mma_tf32(acc[ti][tj], a[ti], bf[tj]);
        }
        __syncthreads();
        if (kc + 3 < nk) load_stage(st, (kc + 3) << 5);
        st = (st == 2) ? 0 : st + 1;
    }

#pragma unroll
    for (int ti = 0; ti < 4; ti++) {
#pragma unroll
        for (int hh = 0; hh < 2; hh++) {
            int row = bm + wm + ti * 16 + gid + 8 * hh;
#pragma unroll
            for (int tj = 0; tj < 4; tj++) {
                int col = bn + wn + tj * 8 + 2 * tig;
                float2 o;
                o.x = acc[ti][tj][2 * hh + 0] + bias[col + 0];
                o.y = acc[ti][tj][2 * hh + 1] + bias[col + 1];
                *(float2*)&C[(size_t)row * N + col] = o;
            }
        }
    }
}

// ---------------------------------------------------------------------------
// FA2-style flash attention, interleaved per-k16-chunk schedule.
// Block = 4 warps x 32 q rows. kv tiles of 64, cp.async 2-stage, 3 CTAs/SM.
// QK^T tf32 (Q rna in regs, K truncated), PV bf16 register-P.
// Row-sums accumulated by a virtual ones-column (9th PV n-tile).
// ---------------------------------------------------------------------------
#define FA_KV  (64 * 68)
#define FA_SMEM (4 * FA_KV * 4)   // 69632 B

__global__ __launch_bounds__(128, 3)
void flash_tf32(const float* __restrict__ qkv, float* __restrict__ out) {
    extern __shared__ float sm[];
    float* Ks = sm;                    // [2][64][68]
    float* Vs = sm + 2 * FA_KV;        // [2][64][68]

    int b = blockIdx.y >> 4, h = blockIdx.y & 15;
    int q0 = blockIdx.x << 7;
    int tid = threadIdx.x, warp = tid >> 5, lane = tid & 31;
    int gid = lane >> 2, tig = lane & 3;
    int wq = warp * 32;

    const size_t rstr = 3 * CD;
    const float* qb = qkv + (size_t)b * CS * rstr + h * CDH;
    const float* kb = qb + CD;
    const float* vb = qb + 2 * CD;
    const float qscale = 1.4426950408889634f * 0.125f;   // log2e / sqrt(dh)

    // ---- stage Q through the K double-buffer (before kv pipeline starts)
    float* Qt = Ks;   // [128][68]
#pragma unroll
    for (int p = 0; p < 16; p++) {
        int id  = tid + p * 128;
        int row = id >> 4;
        int c4  = (id & 15) << 2;
        float4 v = *(const float4*)&qb[(size_t)(q0 + row) * rstr + c4];
        Qt[row * 68 + c4 + 0] = tfbits(v.x * qscale);
        Qt[row * 68 + c4 + 1] = tfbits(v.y * qscale);
        Qt[row * 68 + c4 + 2] = tfbits(v.z * qscale);
        Qt[row * 68 + c4 + 3] = tfbits(v.w * qscale);
    }
    __syncthreads();

    uint32_t qf[2][8][4];
#pragma unroll
    for (int mi = 0; mi < 2; mi++) {
        int r0 = wq + mi * 16 + gid;
#pragma unroll
        for (int g = 0; g < 8; g++) {
            qf[mi][g][0] = __float_as_uint(Qt[r0 * 68 + g * 8 + tig]);
            qf[mi][g][1] = __float_as_uint(Qt[(r0 + 8) * 68 + g * 8 + tig]);
            qf[mi][g][2] = __float_as_uint(Qt[r0 * 68 + g * 8 + tig + 4]);
            qf[mi][g][3] = __float_as_uint(Qt[(r0 + 8) * 68 + g * 8 + tig + 4]);
        }
    }
    __syncthreads();

    auto load_kv = [&](int st, int kt) {
#pragma unroll
        for (int p = 0; p < 8; p++) {
            int id  = tid + p * 128;
            int row = id >> 4;
            int c4  = (id & 15) << 2;
            cp16(smem_u32(&Ks[st * FA_KV + row * 68 + c4]),
                 kb + (size_t)(kt + row) * rstr + c4);
            cp16(smem_u32(&Vs[st * FA_KV + row * 68 + c4]),
                 vb + (size_t)(kt + row) * rstr + c4);
        }
        cp_commit();
    };

    load_kv(0, 0);
    load_kv(1, 64);

    // O accumulators: 8 d-tiles + 1 sum tile
    float o[2][9][4];
#pragma unroll
    for (int mi = 0; mi < 2; mi++)
#pragma unroll
        for (int n = 0; n < 9; n++)
#pragma unroll
            for (int c = 0; c < 4; c++) o[mi][n][c] = 0.f;

    const uint32_t bones = (gid == 0) ? 0x3F803F80u : 0u;
    const int nkt = CS / 64;   // 32

    for (int it = 0; it < nkt; it++) {
        int st = it & 1;
        cp_wait<1>();
        __syncthreads();
        const float* K0 = Ks + st * FA_KV;
        const float* V0 = Vs + st * FA_KV;

#pragma unroll
        for (int t = 0; t < 4; t++) {
            uint32_t pf[2][4];
            // two S n-tiles of this k16 chunk
#pragma unroll
            for (int half = 0; half < 2; half++) {
                int n = 2 * t + half;
                float sc[2][4];
#pragma unroll
                for (int mi = 0; mi < 2; mi++)
#pragma unroll
                    for (int c = 0; c < 4; c++) sc[mi][c] = 0.f;
                int r = n * 8 + gid;
#pragma unroll
                for (int g = 0; g < 8; g++) {
                    uint32_t bf[2];
                    bf[0] = __float_as_uint(K0[r * 68 + g * 8 + tig]);
                    bf[1] = __float_as_uint(K0[r * 68 + g * 8 + tig + 4]);
                    mma_tf32(sc[0], qf[0][g], bf);
                    mma_tf32(sc[1], qf[1][g], bf);
                }
#pragma unroll
                for (int mi = 0; mi < 2; mi++) {
                    pf[mi][half * 2 + 0] = pack_bf16(ex2f(sc[mi][0]), ex2f(sc[mi][1]));
                    pf[mi][half * 2 + 1] = pack_bf16(ex2f(sc[mi][2]), ex2f(sc[mi][3]));
                }
            }
            // PV for this k16 chunk
#pragma unroll
            for (int n = 0; n < 8; n++) {
                uint32_t bv[2];
                int dcol = n * 8 + gid;
                bv[0] = pack_bf16(V0[(16 * t + 2 * tig)     * 68 + dcol],
                                  V0[(16 * t + 2 * tig + 1) * 68 + dcol]);
                bv[1] = pack_bf16(V0[(16 * t + 2 * tig + 8) * 68 + dcol],
                                  V0[(16 * t + 2 * tig + 9) * 68 + dcol]);
                mma_bf16(o[0][n], pf[0], bv);
                mma_bf16(o[1][n], pf[1], bv);
            }
            {   // ones column -> row sums
                uint32_t bv[2] = {bones, bones};
                mma_bf16(o[0][8], pf[0], bv);
                mma_bf16(o[1][8], pf[1], bv);
            }
        }

        __syncthreads();
        if (it + 2 < nkt) load_kv(st, (it + 2) * 64);
    }

    // normalize + write (row sums live in the tig==0 lanes of o[mi][8])
    int base = lane & 28;
#pragma unroll
    for (int mi = 0; mi < 2; mi++)
#pragma unroll
        for (int hh = 0; hh < 2; hh++) {
            float lsv = __shfl_sync(0xffffffffu, o[mi][8][hh ? 2 : 0], base);
            float inv = 1.f / lsv;
            int row = q0 + wq + mi * 16 + gid + 8 * hh;
#pragma unroll
            for (int n = 0; n < 8; n++) {
                int col = h * CDH + n * 8 + 2 * tig;
                float2 ov = make_float2(o[mi][n][2 * hh] * inv,
                                        o[mi][n][2 * hh + 1] * inv);
                *(float2*)&out[((size_t)b * CS + row) * CD + col] = ov;
            }
        }
}

// ---------------------------------------------------------------------------
// Fused residual add + LayerNorm
// ---------------------------------------------------------------------------
__global__ __launch_bounds__(256)
void add_ln(const float* __restrict__ chunk, const float* __restrict__ proj,
            const float* __restrict__ g, const float* __restrict__ beta,
            float* __restrict__ out) {
    int row = blockIdx.x;
    int tid = threadIdx.x;
    size_t base = (size_t)row * CD + tid * 4;

    float4 c = *(const float4*)&chunk[base];
    float4 p = *(const float4*)&proj[base];
    float4 x = make_float4(c.x + p.x, c.y + p.y, c.z + p.z, c.w + p.w);

    float s  = x.x + x.y + x.z + x.w;
    float s2 = x.x * x.x + x.y * x.y + x.z * x.z + x.w * x.w;
#pragma unroll
    for (int off = 16; off; off >>= 1) {
        s  += __shfl_xor_sync(0xffffffffu, s,  off);
        s2 += __shfl_xor_sync(0xffffffffu, s2, off);
    }
    __shared__ float rs[8], rs2[8];
    __shared__ float s_mu, s_rstd;
    int lane = tid & 31, warp = tid >> 5;
    if (lane == 0) { rs[warp] = s; rs2[warp] = s2; }
    __syncthreads();
    if (tid == 0) {
        float a = 0.f, b2 = 0.f;
#pragma unroll
        for (int w = 0; w < 8; w++) { a += rs[w]; b2 += rs2[w]; }
        float mean = a * (1.f / CD);
        float var  = b2 * (1.f / CD) - mean * mean;
        s_mu = mean;
        s_rstd = rsqrtf(var + LN_EPS);
    }
    __syncthreads();
    float mu = s_mu, rstd = s_rstd;

    float4 gv = *(const float4*)&g[tid * 4];
    float4 bv = *(const float4*)&beta[tid * 4];
    float4 y;
    y.x = (x.x - mu) * rstd * gv.x + bv.x;
    y.y = (x.y - mu) * rstd * gv.y + bv.y;
    y.z = (x.z - mu) * rstd * gv.z + bv.z;
    y.w = (x.w - mu) * rstd * gv.w + bv.w;
    *(float4*)&out[base] = y;
}

// ---------------------------------------------------------------------------
extern "C" void kernel_launch(void* const* d_in, const int* in_sizes, int n_in,
                              void* d_out, int out_size) {
    const float* emb     = (const float*)d_in[0];
    const float* chunk_w = (const float*)d_in[1];
    const float* chunk_b = (const float*)d_in[2];
    const float* in_w    = (const float*)d_in[3];
    const float* in_b    = (const float*)d_in[4];
    const float* out_w   = (const float*)d_in[5];
    const float* out_b   = (const float*)d_in[6];
    const float* ln_g    = (const float*)d_in[7];
    const float* ln_b    = (const float*)d_in[8];
    float* out = (float*)d_out;

    float *chunk, *qkv, *attn, *proj;
    cudaGetSymbolAddress((void**)&chunk, g_chunk);
    cudaGetSymbolAddress((void**)&qkv,   g_qkv);
    cudaGetSymbolAddress((void**)&attn,  g_attn);
    cudaGetSymbolAddress((void**)&proj,  g_proj);

    cudaFuncSetAttribute(gemm_tf32<true>,
                         cudaFuncAttributeMaxDynamicSharedMemorySize, GK_SMEM);
    cudaFuncSetAttribute(gemm_tf32<false>,
                         cudaFuncAttributeMaxDynamicSharedMemorySize, GK_SMEM);
    cudaFuncSetAttribute(flash_tf32,
                         cudaFuncAttributeMaxDynamicSharedMemorySize, FA_SMEM);

    // 1) chunk = windows @ chunk_w^T + chunk_b
    {
        dim3 grid(CD / 128, MROWS / 128);
        gemm_tf32<true><<<grid, 256, GK_SMEM>>>(emb, chunk_w, chunk_b, chunk,
                                                MROWS, CD, 2 * CD);
    }
    // 2) qkv = chunk @ in_proj_w^T + in_proj_b
    {
        dim3 grid(3 * CD / 128, MROWS / 128);
        gemm_tf32<false><<<grid, 256, GK_SMEM>>>(chunk, in_w, in_b, qkv,
                                                 MROWS, 3 * CD, CD);
    }
    // 3) flash attention
    {
        dim3 grid(CS / 128, CB * CH);
        flash_tf32<<<grid, 128, FA_SMEM>>>(qkv, attn);
    }
    // 4) proj = attn @ out_proj_w^T + out_proj_b
    {
        dim3 grid(CD / 128, MROWS / 128);
        gemm_tf32<false><<<grid, 256, GK_SMEM>>>(attn, out_w, out_b, proj,
                                                 MROWS, CD, CD);
    }
    // 5) out = LayerNorm(chunk + proj)
    add_ln<<<MROWS, 256>>>(chunk, proj, ln_g, ln_b, out);
}

// round 5
// speedup vs baseline: 1.1060x; 1.1060x over previous
#include <cuda_runtime.h>
#include <math.h>
#include <stdint.h>

#define CB   4
#define CS   2048
#define CD   1024
#define CH   16
#define CDH  64
#define MROWS (CB*CS)
#define LN_EPS 1e-5f

// ---------------- scratch ----------------
__device__ float g_chunk[(size_t)MROWS*CD];
__device__ float g_qkv  [(size_t)MROWS*3*CD];
__device__ float g_attn [(size_t)MROWS*CD];
__device__ float g_proj [(size_t)MROWS*CD];

// ---------------- helpers ----------------
__device__ __forceinline__ uint32_t f2tf(float x) {
    uint32_t u; asm("cvt.rna.tf32.f32 %0, %1;" : "=r"(u) : "f"(x)); return u;
}
__device__ __forceinline__ float tfbits(float x) {
    return __uint_as_float(f2tf(x));
}
__device__ __forceinline__ float ex2f(float x) {
    float y; asm("ex2.approx.f32 %0, %1;" : "=f"(y) : "f"(x)); return y;
}
__device__ __forceinline__ uint32_t pack_bf16(float lo, float hi) {
    uint32_t r; asm("cvt.rn.bf16x2.f32 %0, %1, %2;" : "=r"(r) : "f"(hi), "f"(lo));
    return r;
}
__device__ __forceinline__ void mma_tf32(float c[4], const uint32_t a[4],
                                         const uint32_t b[2]) {
    asm volatile(
        "mma.sync.aligned.m16n8k8.row.col.f32.tf32.tf32.f32 "
        "{%0,%1,%2,%3}, {%4,%5,%6,%7}, {%8,%9}, {%0,%1,%2,%3};\n"
        : "+f"(c[0]), "+f"(c[1]), "+f"(c[2]), "+f"(c[3])
        : "r"(a[0]), "r"(a[1]), "r"(a[2]), "r"(a[3]), "r"(b[0]), "r"(b[1]));
}
__device__ __forceinline__ void mma_bf16(float c[4], const uint32_t a[4],
                                         const uint32_t b[2]) {
    asm volatile(
        "mma.sync.aligned.m16n8k16.row.col.f32.bf16.bf16.f32 "
        "{%0,%1,%2,%3}, {%4,%5,%6,%7}, {%8,%9}, {%0,%1,%2,%3};\n"
        : "+f"(c[0]), "+f"(c[1]), "+f"(c[2]), "+f"(c[3])
        : "r"(a[0]), "r"(a[1]), "r"(a[2]), "r"(a[3]), "r"(b[0]), "r"(b[1]));
}
__device__ __forceinline__ uint32_t smem_u32(const void* p) {
    return (uint32_t)__cvta_generic_to_shared(p);
}
__device__ __forceinline__ void cp16(uint32_t dst, const void* src) {
    asm volatile("cp.async.cg.shared.global [%0], [%1], 16;\n"
                 :: "r"(dst), "l"(src));
}
__device__ __forceinline__ void cp16z(uint32_t dst, const void* src, int srcsz) {
    asm volatile("cp.async.cg.shared.global [%0], [%1], 16, %2;\n"
                 :: "r"(dst), "l"(src), "r"(srcsz));
}
__device__ __forceinline__ void cp_commit() {
    asm volatile("cp.async.commit_group;\n");
}
template<int N> __device__ __forceinline__ void cp_wait() {
    asm volatile("cp.async.wait_group %0;\n" :: "n"(N));
}

// ---------------------------------------------------------------------------
// TF32 NT GEMM, cp.async double-buffered (exact R3 revert): C = A @ B^T + bias
// 128x128x32 tile, 256 threads, warp tile 64x32; per-fragment rna cvt.
// ---------------------------------------------------------------------------
#define GK_SMEM (2 * 2 * 128 * 36 * 4)

template<bool WINDOW>
__global__ __launch_bounds__(256, 2)
void gemm_tf32(const float* __restrict__ A, const float* __restrict__ B,
               const float* __restrict__ bias, float* __restrict__ C,
               int M, int N, int K) {
    extern __shared__ float sm[];
    float* As = sm;                 // [2][128][36]
    float* Bs = sm + 2 * 128 * 36;  // [2][128][36]

    int tid = threadIdx.x;
    int bm = blockIdx.y * 128, bn = blockIdx.x * 128;
    int warp = tid >> 5, lane = tid & 31, gid = lane >> 2, tig = lane & 3;
    int wm = (warp >> 2) * 64, wn = (warp & 3) * 32;

    float acc[4][4][4];
#pragma unroll
    for (int i = 0; i < 4; i++)
#pragma unroll
        for (int j = 0; j < 4; j++)
#pragma unroll
            for (int c = 0; c < 4; c++) acc[i][j][c] = 0.f;

    auto load_stage = [&](int st, int k0) {
#pragma unroll
        for (int p = 0; p < 4; p++) {
            int id  = tid + p * 256;
            int row = id >> 3;
            int kq  = (id & 7) << 2;
            uint32_t da = smem_u32(&As[(st * 128 + row) * 36 + kq]);
            if (WINDOW) {
                int m = bm + row;
                int bidx = m >> 11, s = m & (CS - 1);
                int f = k0 + kq, kk = f >> 10, j = f & (CD - 1);
                const float* src = A + (((size_t)bidx * CS + s + kk) << 10) + j;
                cp16z(da, src, (s + kk < CS) ? 16 : 0);
            } else {
                cp16(da, A + (size_t)(bm + row) * K + k0 + kq);
            }
            cp16(smem_u32(&Bs[(st * 128 + row) * 36 + kq]),
                 B + (size_t)(bn + row) * K + k0 + kq);
        }
        cp_commit();
    };

    int nk = K >> 5;
    load_stage(0, 0);
    load_stage(1, 32);

    for (int kc = 0; kc < nk; kc++) {
        int st = kc & 1;
        cp_wait<1>();
        __syncthreads();
        const float* Ab = As + st * 128 * 36;
        const float* Bb = Bs + st * 128 * 36;
#pragma unroll
        for (int g = 0; g < 32; g += 8) {
            uint32_t a[4][4], bf[4][2];
#pragma unroll
            for (int ti = 0; ti < 4; ti++) {
                int m0 = wm + ti * 16 + gid;
                a[ti][0] = f2tf(Ab[m0 * 36 + g + tig]);
                a[ti][1] = f2tf(Ab[(m0 + 8) * 36 + g + tig]);
                a[ti][2] = f2tf(Ab[m0 * 36 + g + tig + 4]);
                a[ti][3] = f2tf(Ab[(m0 + 8) * 36 + g + tig + 4]);
            }
#pragma unroll
            for (int tj = 0; tj < 4; tj++) {
                int n0 = wn + tj * 8 + gid;
                bf[tj][0] = f2tf(Bb[n0 * 36 + g + tig]);
                bf[tj][1] = f2tf(Bb[n0 * 36 + g + tig + 4]);
            }
#pragma unroll
            for (int ti = 0; ti < 4; ti++)
#pragma unroll
                for (int tj = 0; tj < 4; tj++)
                    mma_tf32(acc[ti][tj], a[ti], bf[tj]);
        }
        __syncthreads();
        if (kc + 2 < nk) load_stage(st, (kc + 2) << 5);
    }

#pragma unroll
    for (int ti = 0; ti < 4; ti++) {
#pragma unroll
        for (int hh = 0; hh < 2; hh++) {
            int row = bm + wm + ti * 16 + gid + 8 * hh;
#pragma unroll
            for (int tj = 0; tj < 4; tj++) {
                int col = bn + wn + tj * 8 + 2 * tig;
                float2 o;
                o.x = acc[ti][tj][2 * hh + 0] + bias[col + 0];
                o.y = acc[ti][tj][2 * hh + 1] + bias[col + 1];
                *(float2*)&C[(size_t)row * N + col] = o;
            }
        }
    }
}

// ---------------------------------------------------------------------------
// FA2-style flash attention. 8 warps x 16 q-rows = 128 q rows per CTA.
// R3 phase structure (full-ILP S phase), mi=1 for low regs -> 2 CTAs/SM of
// 256 thr = 4 warps/SMSP. kv tiles of 64, cp.async 2-stage.
// QK^T tf32, PV bf16 register-P, row-sums via ones-column.
// ---------------------------------------------------------------------------
#define FA_KV  (64 * 68)
#define FA_SMEM (4 * FA_KV * 4)   // 69632 B

__global__ __launch_bounds__(256, 2)
void flash_tf32(const float* __restrict__ qkv, float* __restrict__ out) {
    extern __shared__ float sm[];
    float* Ks = sm;                    // [2][64][68]
    float* Vs = sm + 2 * FA_KV;        // [2][64][68]

    int b = blockIdx.y >> 4, h = blockIdx.y & 15;
    int q0 = blockIdx.x << 7;
    int tid = threadIdx.x, warp = tid >> 5, lane = tid & 31;
    int gid = lane >> 2, tig = lane & 3;
    int wq = warp * 16;

    const size_t rstr = 3 * CD;
    const float* qb = qkv + (size_t)b * CS * rstr + h * CDH;
    const float* kb = qb + CD;
    const float* vb = qb + 2 * CD;
    const float qscale = 1.4426950408889634f * 0.125f;   // log2e / sqrt(dh)

    // ---- stage Q through the K double-buffer (128*68 == 2*FA_KV)
    float* Qt = Ks;
#pragma unroll
    for (int p = 0; p < 8; p++) {
        int id  = tid + p * 256;
        int row = id >> 4;
        int c4  = (id & 15) << 2;
        float4 v = *(const float4*)&qb[(size_t)(q0 + row) * rstr + c4];
        Qt[row * 68 + c4 + 0] = tfbits(v.x * qscale);
        Qt[row * 68 + c4 + 1] = tfbits(v.y * qscale);
        Qt[row * 68 + c4 + 2] = tfbits(v.z * qscale);
        Qt[row * 68 + c4 + 3] = tfbits(v.w * qscale);
    }
    __syncthreads();

    uint32_t qf[8][4];
    {
        int r0 = wq + gid;
#pragma unroll
        for (int g = 0; g < 8; g++) {
            qf[g][0] = __float_as_uint(Qt[r0 * 68 + g * 8 + tig]);
            qf[g][1] = __float_as_uint(Qt[(r0 + 8) * 68 + g * 8 + tig]);
            qf[g][2] = __float_as_uint(Qt[r0 * 68 + g * 8 + tig + 4]);
            qf[g][3] = __float_as_uint(Qt[(r0 + 8) * 68 + g * 8 + tig + 4]);
        }
    }
    __syncthreads();

    auto load_kv = [&](int st, int kt) {
#pragma unroll
        for (int p = 0; p < 4; p++) {
            int id  = tid + p * 256;
            int row = id >> 4;
            int c4  = (id & 15) << 2;
            cp16(smem_u32(&Ks[st * FA_KV + row * 68 + c4]),
                 kb + (size_t)(kt + row) * rstr + c4);
            cp16(smem_u32(&Vs[st * FA_KV + row * 68 + c4]),
                 vb + (size_t)(kt + row) * rstr + c4);
        }
        cp_commit();
    };

    load_kv(0, 0);
    load_kv(1, 64);

    // O accumulators: 8 d-tiles + 1 ones (row-sum) tile
    float o[9][4];
#pragma unroll
    for (int n = 0; n < 9; n++)
#pragma unroll
        for (int c = 0; c < 4; c++) o[n][c] = 0.f;

    const uint32_t bones = (gid == 0) ? 0x3F803F80u : 0u;
    const int nkt = CS / 64;   // 32

    for (int it = 0; it < nkt; it++) {
        int st = it & 1;
        cp_wait<1>();
        __syncthreads();
        const float* K0 = Ks + st * FA_KV;
        const float* V0 = Vs + st * FA_KV;

        // S = Q @ K^T : 8 independent accumulator chains, g-outer
        float sc[8][4];
#pragma unroll
        for (int n = 0; n < 8; n++)
#pragma unroll
            for (int c = 0; c < 4; c++) sc[n][c] = 0.f;
#pragma unroll
        for (int g = 0; g < 8; g++) {
#pragma unroll
            for (int n = 0; n < 8; n++) {
                int r = n * 8 + gid;
                uint32_t bf[2];
                bf[0] = __float_as_uint(K0[r * 68 + g * 8 + tig]);
                bf[1] = __float_as_uint(K0[r * 68 + g * 8 + tig + 4]);
                mma_tf32(sc[n], qf[g], bf);
            }
        }

        // P = exp2(S) packed directly into bf16 A-fragments
        uint32_t pf[4][4];
#pragma unroll
        for (int n = 0; n < 8; n++) {
            int t = n >> 1, hi = (n & 1) << 1;
            pf[t][hi + 0] = pack_bf16(ex2f(sc[n][0]), ex2f(sc[n][1]));
            pf[t][hi + 1] = pack_bf16(ex2f(sc[n][2]), ex2f(sc[n][3]));
        }

        // O += P @ V : 9 independent chains of length 4
#pragma unroll
        for (int t = 0; t < 4; t++) {
#pragma unroll
            for (int n = 0; n < 8; n++) {
                uint32_t bv[2];
                int dcol = n * 8 + gid;
                bv[0] = pack_bf16(V0[(16 * t + 2 * tig)     * 68 + dcol],
                                  V0[(16 * t + 2 * tig + 1) * 68 + dcol]);
                bv[1] = pack_bf16(V0[(16 * t + 2 * tig + 8) * 68 + dcol],
                                  V0[(16 * t + 2 * tig + 9) * 68 + dcol]);
                mma_bf16(o[n], pf[t], bv);
            }
            {
                uint32_t bv[2] = {bones, bones};
                mma_bf16(o[8], pf[t], bv);
            }
        }

        __syncthreads();
        if (it + 2 < nkt) load_kv(st, (it + 2) * 64);
    }

    // normalize + write (row sums in tig==0 lanes of o[8])
    int base = lane & 28;
#pragma unroll
    for (int hh = 0; hh < 2; hh++) {
        float lsv = __shfl_sync(0xffffffffu, o[8][hh ? 2 : 0], base);
        float inv = 1.f / lsv;
        int row = q0 + wq + gid + 8 * hh;
#pragma unroll
        for (int n = 0; n < 8; n++) {
            int col = h * CDH + n * 8 + 2 * tig;
            float2 ov = make_float2(o[n][2 * hh] * inv,
                                    o[n][2 * hh + 1] * inv);
            *(float2*)&out[((size_t)b * CS + row) * CD + col] = ov;
        }
    }
}

// ---------------------------------------------------------------------------
// Fused residual add + LayerNorm
// ---------------------------------------------------------------------------
__global__ __launch_bounds__(256)
void add_ln(const float* __restrict__ chunk, const float* __restrict__ proj,
            const float* __restrict__ g, const float* __restrict__ beta,
            float* __restrict__ out) {
    int row = blockIdx.x;
    int tid = threadIdx.x;
    size_t base = (size_t)row * CD + tid * 4;

    float4 c = *(const float4*)&chunk[base];
    float4 p = *(const float4*)&proj[base];
    float4 x = make_float4(c.x + p.x, c.y + p.y, c.z + p.z, c.w + p.w);

    float s  = x.x + x.y + x.z + x.w;
    float s2 = x.x * x.x + x.y * x.y + x.z * x.z + x.w * x.w;
#pragma unroll
    for (int off = 16; off; off >>= 1) {
        s  += __shfl_xor_sync(0xffffffffu, s,  off);
        s2 += __shfl_xor_sync(0xffffffffu, s2, off);
    }
    __shared__ float rs[8], rs2[8];
    __shared__ float s_mu, s_rstd;
    int lane = tid & 31, warp = tid >> 5;
    if (lane == 0) { rs[warp] = s; rs2[warp] = s2; }
    __syncthreads();
    if (tid == 0) {
        float a = 0.f, b2 = 0.f;
#pragma unroll
        for (int w = 0; w < 8; w++) { a += rs[w]; b2 += rs2[w]; }
        float mean = a * (1.f / CD);
        float var  = b2 * (1.f / CD) - mean * mean;
        s_mu = mean;
        s_rstd = rsqrtf(var + LN_EPS);
    }
    __syncthreads();
    float mu = s_mu, rstd = s_rstd;

    float4 gv = *(const float4*)&g[tid * 4];
    float4 bv = *(const float4*)&beta[tid * 4];
    float4 y;
    y.x = (x.x - mu) * rstd * gv.x + bv.x;
    y.y = (x.y - mu) * rstd * gv.y + bv.y;
    y.z = (x.z - mu) * rstd * gv.z + bv.z;
    y.w = (x.w - mu) * rstd * gv.w + bv.w;
    *(float4*)&out[base] = y;
}

// ---------------------------------------------------------------------------
extern "C" void kernel_launch(void* const* d_in, const int* in_sizes, int n_in,
                              void* d_out, int out_size) {
    const float* emb     = (const float*)d_in[0];
    const float* chunk_w = (const float*)d_in[1];
    const float* chunk_b = (const float*)d_in[2];
    const float* in_w    = (const float*)d_in[3];
    const float* in_b    = (const float*)d_in[4];
    const float* out_w   = (const float*)d_in[5];
    const float* out_b   = (const float*)d_in[6];
    const float* ln_g    = (const float*)d_in[7];
    const float* ln_b    = (const float*)d_in[8];
    float* out = (float*)d_out;

    float *chunk, *qkv, *attn, *proj;
    cudaGetSymbolAddress((void**)&chunk, g_chunk);
    cudaGetSymbolAddress((void**)&qkv,   g_qkv);
    cudaGetSymbolAddress((void**)&attn,  g_attn);
    cudaGetSymbolAddress((void**)&proj,  g_proj);

    cudaFuncSetAttribute(gemm_tf32<true>,
                         cudaFuncAttributeMaxDynamicSharedMemorySize, GK_SMEM);
    cudaFuncSetAttribute(gemm_tf32<false>,
                         cudaFuncAttributeMaxDynamicSharedMemorySize, GK_SMEM);
    cudaFuncSetAttribute(flash_tf32,
                         cudaFuncAttributeMaxDynamicSharedMemorySize, FA_SMEM);

    // 1) chunk = windows @ chunk_w^T + chunk_b
    {
        dim3 grid(CD / 128, MROWS / 128);
        gemm_tf32<true><<<grid, 256, GK_SMEM>>>(emb, chunk_w, chunk_b, chunk,
                                                MROWS, CD, 2 * CD);
    }
    // 2) qkv = chunk @ in_proj_w^T + in_proj_b
    {
        dim3 grid(3 * CD / 128, MROWS / 128);
        gemm_tf32<false><<<grid, 256, GK_SMEM>>>(chunk, in_w, in_b, qkv,
                                                 MROWS, 3 * CD, CD);
    }
    // 3) flash attention
    {
        dim3 grid(CS / 128, CB * CH);
        flash_tf32<<<grid, 256, FA_SMEM>>>(qkv, attn);
    }
    // 4) proj = attn @ out_proj_w^T + out_proj_b
    {
        dim3 grid(CD / 128, MROWS / 128);
        gemm_tf32<false><<<grid, 256, GK_SMEM>>>(attn, out_w, out_b, proj,
                                                 MROWS, CD, CD);
    }
    // 5) out = LayerNorm(chunk + proj)
    add_ln<<<MROWS, 256>>>(chunk, proj, ln_g, ln_b, out);
}

// round 6
// speedup vs baseline: 1.1250x; 1.0172x over previous
#include <cuda_runtime.h>
#include <math.h>
#include <stdint.h>

#define CB   4
#define CS   2048
#define CD   1024
#define CH   16
#define CDH  64
#define MROWS (CB*CS)
#define LN_EPS 1e-5f

// ---------------- scratch ----------------
__device__ float g_chunk[(size_t)MROWS*CD];
__device__ float g_qkv  [(size_t)MROWS*3*CD];
__device__ float g_attn [(size_t)MROWS*CD];
__device__ float g_proj [(size_t)MROWS*CD];

// ---------------- helpers ----------------
__device__ __forceinline__ uint32_t f2tf(float x) {
    uint32_t u; asm("cvt.rna.tf32.f32 %0, %1;" : "=r"(u) : "f"(x)); return u;
}
__device__ __forceinline__ float tfbits(float x) {
    return __uint_as_float(f2tf(x));
}
__device__ __forceinline__ float ex2f(float x) {
    float y; asm("ex2.approx.f32 %0, %1;" : "=f"(y) : "f"(x)); return y;
}
__device__ __forceinline__ uint32_t pack_bf16(float lo, float hi) {
    uint32_t r; asm("cvt.rn.bf16x2.f32 %0, %1, %2;" : "=r"(r) : "f"(hi), "f"(lo));
    return r;
}
__device__ __forceinline__ void mma_tf32(float c[4], const uint32_t a[4],
                                         const uint32_t b[2]) {
    asm volatile(
        "mma.sync.aligned.m16n8k8.row.col.f32.tf32.tf32.f32 "
        "{%0,%1,%2,%3}, {%4,%5,%6,%7}, {%8,%9}, {%0,%1,%2,%3};\n"
        : "+f"(c[0]), "+f"(c[1]), "+f"(c[2]), "+f"(c[3])
        : "r"(a[0]), "r"(a[1]), "r"(a[2]), "r"(a[3]), "r"(b[0]), "r"(b[1]));
}
__device__ __forceinline__ void mma_bf16(float c[4], const uint32_t a[4],
                                         const uint32_t b[2]) {
    asm volatile(
        "mma.sync.aligned.m16n8k16.row.col.f32.bf16.bf16.f32 "
        "{%0,%1,%2,%3}, {%4,%5,%6,%7}, {%8,%9}, {%0,%1,%2,%3};\n"
        : "+f"(c[0]), "+f"(c[1]), "+f"(c[2]), "+f"(c[3])
        : "r"(a[0]), "r"(a[1]), "r"(a[2]), "r"(a[3]), "r"(b[0]), "r"(b[1]));
}
__device__ __forceinline__ void ldsm_x4(uint32_t& r0, uint32_t& r1,
                                        uint32_t& r2, uint32_t& r3,
                                        uint32_t addr) {
    asm volatile("ldmatrix.sync.aligned.m8n8.x4.shared.b16 {%0,%1,%2,%3}, [%4];\n"
                 : "=r"(r0), "=r"(r1), "=r"(r2), "=r"(r3) : "r"(addr));
}
__device__ __forceinline__ void ldsm_x4_t(uint32_t& r0, uint32_t& r1,
                                          uint32_t& r2, uint32_t& r3,
                                          uint32_t addr) {
    asm volatile("ldmatrix.sync.aligned.m8n8.x4.trans.shared.b16 {%0,%1,%2,%3}, [%4];\n"
                 : "=r"(r0), "=r"(r1), "=r"(r2), "=r"(r3) : "r"(addr));
}
__device__ __forceinline__ uint32_t smem_u32(const void* p) {
    return (uint32_t)__cvta_generic_to_shared(p);
}
__device__ __forceinline__ void cp16(uint32_t dst, const void* src) {
    asm volatile("cp.async.cg.shared.global [%0], [%1], 16;\n"
                 :: "r"(dst), "l"(src));
}
__device__ __forceinline__ void cp16z(uint32_t dst, const void* src, int srcsz) {
    asm volatile("cp.async.cg.shared.global [%0], [%1], 16, %2;\n"
                 :: "r"(dst), "l"(src), "r"(srcsz));
}
__device__ __forceinline__ void cp_commit() {
    asm volatile("cp.async.commit_group;\n");
}
template<int N> __device__ __forceinline__ void cp_wait() {
    asm volatile("cp.async.wait_group %0;\n" :: "n"(N));
}

// ---------------------------------------------------------------------------
// TF32 NT GEMM, cp.async double-buffered (best-known from R3): C = A@B^T+bias
// ---------------------------------------------------------------------------
#define GK_SMEM (2 * 2 * 128 * 36 * 4)

template<bool WINDOW>
__global__ __launch_bounds__(256, 2)
void gemm_tf32(const float* __restrict__ A, const float* __restrict__ B,
               const float* __restrict__ bias, float* __restrict__ C,
               int M, int N, int K) {
    extern __shared__ float sm[];
    float* As = sm;                 // [2][128][36]
    float* Bs = sm + 2 * 128 * 36;  // [2][128][36]

    int tid = threadIdx.x;
    int bm = blockIdx.y * 128, bn = blockIdx.x * 128;
    int warp = tid >> 5, lane = tid & 31, gid = lane >> 2, tig = lane & 3;
    int wm = (warp >> 2) * 64, wn = (warp & 3) * 32;

    float acc[4][4][4];
#pragma unroll
    for (int i = 0; i < 4; i++)
#pragma unroll
        for (int j = 0; j < 4; j++)
#pragma unroll
            for (int c = 0; c < 4; c++) acc[i][j][c] = 0.f;

    auto load_stage = [&](int st, int k0) {
#pragma unroll
        for (int p = 0; p < 4; p++) {
            int id  = tid + p * 256;
            int row = id >> 3;
            int kq  = (id & 7) << 2;
            uint32_t da = smem_u32(&As[(st * 128 + row) * 36 + kq]);
            if (WINDOW) {
                int m = bm + row;
                int bidx = m >> 11, s = m & (CS - 1);
                int f = k0 + kq, kk = f >> 10, j = f & (CD - 1);
                const float* src = A + (((size_t)bidx * CS + s + kk) << 10) + j;
                cp16z(da, src, (s + kk < CS) ? 16 : 0);
            } else {
                cp16(da, A + (size_t)(bm + row) * K + k0 + kq);
            }
            cp16(smem_u32(&Bs[(st * 128 + row) * 36 + kq]),
                 B + (size_t)(bn + row) * K + k0 + kq);
        }
        cp_commit();
    };

    int nk = K >> 5;
    load_stage(0, 0);
    load_stage(1, 32);

    for (int kc = 0; kc < nk; kc++) {
        int st = kc & 1;
        cp_wait<1>();
        __syncthreads();
        const float* Ab = As + st * 128 * 36;
        const float* Bb = Bs + st * 128 * 36;
#pragma unroll
        for (int g = 0; g < 32; g += 8) {
            uint32_t a[4][4], bf[4][2];
#pragma unroll
            for (int ti = 0; ti < 4; ti++) {
                int m0 = wm + ti * 16 + gid;
                a[ti][0] = f2tf(Ab[m0 * 36 + g + tig]);
                a[ti][1] = f2tf(Ab[(m0 + 8) * 36 + g + tig]);
                a[ti][2] = f2tf(Ab[m0 * 36 + g + tig + 4]);
                a[ti][3] = f2tf(Ab[(m0 + 8) * 36 + g + tig + 4]);
            }
#pragma unroll
            for (int tj = 0; tj < 4; tj++) {
                int n0 = wn + tj * 8 + gid;
                bf[tj][0] = f2tf(Bb[n0 * 36 + g + tig]);
                bf[tj][1] = f2tf(Bb[n0 * 36 + g + tig + 4]);
            }
#pragma unroll
            for (int ti = 0; ti < 4; ti++)
#pragma unroll
                for (int tj = 0; tj < 4; tj++)
                    mma_tf32(acc[ti][tj], a[ti], bf[tj]);
        }
        __syncthreads();
        if (kc + 2 < nk) load_stage(st, (kc + 2) << 5);
    }

#pragma unroll
    for (int ti = 0; ti < 4; ti++) {
#pragma unroll
        for (int hh = 0; hh < 2; hh++) {
            int row = bm + wm + ti * 16 + gid + 8 * hh;
#pragma unroll
            for (int tj = 0; tj < 4; tj++) {
                int col = bn + wn + tj * 8 + 2 * tig;
                float2 o;
                o.x = acc[ti][tj][2 * hh + 0] + bias[col + 0];
                o.y = acc[ti][tj][2 * hh + 1] + bias[col + 1];
                *(float2*)&C[(size_t)row * N + col] = o;
            }
        }
    }
}

// ---------------------------------------------------------------------------
// Flash attention with LDSM fragment loads.
// 8 warps x 16 q-rows, 256 thr, 2 CTAs/SM. kv tiles of 64, cp.async 2-stage.
// K fragments: ldmatrix.x4 on f32-as-b16 (tf32 trick).
// V: in-place convert to bf16 [64][72] overlay, then ldmatrix.x4.trans.
// Row-sums via ones-column (9th PV accumulator).
// ---------------------------------------------------------------------------
#define FA_KV  (64 * 68)
#define FA_SMEM (4 * FA_KV * 4)   // 69632 B

__global__ __launch_bounds__(256, 2)
void flash_tf32(const float* __restrict__ qkv, float* __restrict__ out) {
    extern __shared__ float sm[];
    float* Ks = sm;                    // [2][64][68] f32
    float* Vs = sm + 2 * FA_KV;        // [2][64][68] f32 raw; bf16 overlay [64][72]

    int b = blockIdx.y >> 4, h = blockIdx.y & 15;
    int q0 = blockIdx.x << 7;
    int tid = threadIdx.x, warp = tid >> 5, lane = tid & 31;
    int gid = lane >> 2, tig = lane & 3;
    int wq = warp * 16;
    int l7 = lane & 7, l3 = lane >> 3;

    const size_t rstr = 3 * CD;
    const float* qb = qkv + (size_t)b * CS * rstr + h * CDH;
    const float* kb = qb + CD;
    const float* vb = qb + 2 * CD;
    const float qscale = 1.4426950408889634f * 0.125f;   // log2e / sqrt(dh)

    // ---- stage Q through the K double-buffer (128*68 == 2*FA_KV)
    float* Qt = Ks;
#pragma unroll
    for (int p = 0; p < 8; p++) {
        int id  = tid + p * 256;
        int row = id >> 4;
        int c4  = (id & 15) << 2;
        float4 v = *(const float4*)&qb[(size_t)(q0 + row) * rstr + c4];
        Qt[row * 68 + c4 + 0] = tfbits(v.x * qscale);
        Qt[row * 68 + c4 + 1] = tfbits(v.y * qscale);
        Qt[row * 68 + c4 + 2] = tfbits(v.z * qscale);
        Qt[row * 68 + c4 + 3] = tfbits(v.w * qscale);
    }
    __syncthreads();

    uint32_t qf[8][4];
    {
        int r0 = wq + gid;
#pragma unroll
        for (int g = 0; g < 8; g++) {
            qf[g][0] = __float_as_uint(Qt[r0 * 68 + g * 8 + tig]);
            qf[g][1] = __float_as_uint(Qt[(r0 + 8) * 68 + g * 8 + tig]);
            qf[g][2] = __float_as_uint(Qt[r0 * 68 + g * 8 + tig + 4]);
            qf[g][3] = __float_as_uint(Qt[(r0 + 8) * 68 + g * 8 + tig + 4]);
        }
    }
    __syncthreads();

    auto load_kv = [&](int st, int kt) {
#pragma unroll
        for (int p = 0; p < 4; p++) {
            int id  = tid + p * 256;
            int row = id >> 4;
            int c4  = (id & 15) << 2;
            cp16(smem_u32(&Ks[st * FA_KV + row * 68 + c4]),
                 kb + (size_t)(kt + row) * rstr + c4);
            cp16(smem_u32(&Vs[st * FA_KV + row * 68 + c4]),
                 vb + (size_t)(kt + row) * rstr + c4);
        }
        cp_commit();
    };

    load_kv(0, 0);
    load_kv(1, 64);

    // O accumulators: 8 d-tiles + 1 ones (row-sum) tile
    float o[9][4];
#pragma unroll
    for (int n = 0; n < 9; n++)
#pragma unroll
        for (int c = 0; c < 4; c++) o[n][c] = 0.f;

    const uint32_t bones = (gid == 0) ? 0x3F803F80u : 0u;
    const int nkt = CS / 64;   // 32

    for (int it = 0; it < nkt; it++) {
        int st = it & 1;
        cp_wait<1>();
        __syncthreads();
        uint32_t Kbase = smem_u32(Ks + st * FA_KV);
        float*   V0f   = Vs + st * FA_KV;
        uint32_t Vbase = smem_u32(V0f);   // bf16 overlay [64][72] at stage base

        // ---- V convert: raw f32 [64][68] -> bf16 [64][72] overlay (in place)
        float vr[4][4];
#pragma unroll
        for (int p = 0; p < 4; p++) {
            int id  = tid + p * 256;
            int row = id >> 4;
            int c4  = (id & 15) << 2;
            *(float4*)vr[p] = *(const float4*)&V0f[row * 68 + c4];
        }
        __syncthreads();
#pragma unroll
        for (int p = 0; p < 4; p++) {
            int id  = tid + p * 256;
            int row = id >> 4;
            int c4  = (id & 15) << 2;
            uint32_t* dst = (uint32_t*)V0f + row * 36 + (c4 >> 1);
            dst[0] = pack_bf16(vr[p][0], vr[p][1]);
            dst[1] = pack_bf16(vr[p][2], vr[p][3]);
        }

        // ---- S = Q @ K^T per n-pair, exp -> pf (bf16 A-fragments)
        uint32_t pf[4][4];
#pragma unroll
        for (int np = 0; np < 4; np++) {
            uint32_t kf[2][8][2];
#pragma unroll
            for (int nn = 0; nn < 2; nn++) {
                int n = 2 * np + nn;
                uint32_t rowadr = Kbase + ((n * 8 + l7) * 68 + l3 * 4) * 4;
#pragma unroll
                for (int j = 0; j < 4; j++)
                    ldsm_x4(kf[nn][2*j][0], kf[nn][2*j][1],
                            kf[nn][2*j+1][0], kf[nn][2*j+1][1],
                            rowadr + j * 64);
            }
            float sc[2][4];
#pragma unroll
            for (int nn = 0; nn < 2; nn++)
#pragma unroll
                for (int c = 0; c < 4; c++) sc[nn][c] = 0.f;
#pragma unroll
            for (int g = 0; g < 8; g++) {
                mma_tf32(sc[0], qf[g], kf[0][g]);
                mma_tf32(sc[1], qf[g], kf[1][g]);
            }
            pf[np][0] = pack_bf16(ex2f(sc[0][0]), ex2f(sc[0][1]));
            pf[np][1] = pack_bf16(ex2f(sc[0][2]), ex2f(sc[0][3]));
            pf[np][2] = pack_bf16(ex2f(sc[1][0]), ex2f(sc[1][1]));
            pf[np][3] = pack_bf16(ex2f(sc[1][2]), ex2f(sc[1][3]));
        }

        __syncthreads();   // V16 writes visible to all warps

        // ---- O += P @ V via ldmatrix.trans on bf16 V
#pragma unroll
        for (int t = 0; t < 4; t++) {
#pragma unroll
            for (int a = 0; a < 4; a++) {
                // tiles: (rows 16t + (l3&1)*8 + l7, cols (2a + (l3>>1))*8)
                uint32_t adr = Vbase +
                    (16 * t + (l3 & 1) * 8 + l7) * 144 +
                    (2 * a + (l3 >> 1)) * 16;
                uint32_t v0, v1, v2, v3;
                ldsm_x4_t(v0, v1, v2, v3, adr);
                uint32_t bv0[2] = {v0, v1};
                uint32_t bv1[2] = {v2, v3};
                mma_bf16(o[2*a],     pf[t], bv0);
                mma_bf16(o[2*a + 1], pf[t], bv1);
            }
            {
                uint32_t bv[2] = {bones, bones};
                mma_bf16(o[8], pf[t], bv);
            }
        }

        __syncthreads();
        if (it + 2 < nkt) load_kv(st, (it + 2) * 64);
    }

    // normalize + write (row sums in tig==0 lanes of o[8])
    int base = lane & 28;
#pragma unroll
    for (int hh = 0; hh < 2; hh++) {
        float lsv = __shfl_sync(0xffffffffu, o[8][hh ? 2 : 0], base);
        float inv = 1.f / lsv;
        int row = q0 + wq + gid + 8 * hh;
#pragma unroll
        for (int n = 0; n < 8; n++) {
            int col = h * CDH + n * 8 + 2 * tig;
            float2 ov = make_float2(o[n][2 * hh] * inv,
                                    o[n][2 * hh + 1] * inv);
            *(float2*)&out[((size_t)b * CS + row) * CD + col] = ov;
        }
    }
}

// ---------------------------------------------------------------------------
// Fused residual add + LayerNorm
// ---------------------------------------------------------------------------
__global__ __launch_bounds__(256)
void add_ln(const float* __restrict__ chunk, const float* __restrict__ proj,
            const float* __restrict__ g, const float* __restrict__ beta,
            float* __restrict__ out) {
    int row = blockIdx.x;
    int tid = threadIdx.x;
    size_t base = (size_t)row * CD + tid * 4;

    float4 c = *(const float4*)&chunk[base];
    float4 p = *(const float4*)&proj[base];
    float4 x = make_float4(c.x + p.x, c.y + p.y, c.z + p.z, c.w + p.w);

    float s  = x.x + x.y + x.z + x.w;
    float s2 = x.x * x.x + x.y * x.y + x.z * x.z + x.w * x.w;
#pragma unroll
    for (int off = 16; off; off >>= 1) {
        s  += __shfl_xor_sync(0xffffffffu, s,  off);
        s2 += __shfl_xor_sync(0xffffffffu, s2, off);
    }
    __shared__ float rs[8], rs2[8];
    __shared__ float s_mu, s_rstd;
    int lane = tid & 31, warp = tid >> 5;
    if (lane == 0) { rs[warp] = s; rs2[warp] = s2; }
    __syncthreads();
    if (tid == 0) {
        float a = 0.f, b2 = 0.f;
#pragma unroll
        for (int w = 0; w < 8; w++) { a += rs[w]; b2 += rs2[w]; }
        float mean = a * (1.f / CD);
        float var  = b2 * (1.f / CD) - mean * mean;
        s_mu = mean;
        s_rstd = rsqrtf(var + LN_EPS);
    }
    __syncthreads();
    float mu = s_mu, rstd = s_rstd;

    float4 gv = *(const float4*)&g[tid * 4];
    float4 bv = *(const float4*)&beta[tid * 4];
    float4 y;
    y.x = (x.x - mu) * rstd * gv.x + bv.x;
    y.y = (x.y - mu) * rstd * gv.y + bv.y;
    y.z = (x.z - mu) * rstd * gv.z + bv.z;
    y.w = (x.w - mu) * rstd * gv.w + bv.w;
    *(float4*)&out[base] = y;
}

// ---------------------------------------------------------------------------
extern "C" void kernel_launch(void* const* d_in, const int* in_sizes, int n_in,
                              void* d_out, int out_size) {
    const float* emb     = (const float*)d_in[0];
    const float* chunk_w = (const float*)d_in[1];
    const float* chunk_b = (const float*)d_in[2];
    const float* in_w    = (const float*)d_in[3];
    const float* in_b    = (const float*)d_in[4];
    const float* out_w   = (const float*)d_in[5];
    const float* out_b   = (const float*)d_in[6];
    const float* ln_g    = (const float*)d_in[7];
    const float* ln_b    = (const float*)d_in[8];
    float* out = (float*)d_out;

    float *chunk, *qkv, *attn, *proj;
    cudaGetSymbolAddress((void**)&chunk, g_chunk);
    cudaGetSymbolAddress((void**)&qkv,   g_qkv);
    cudaGetSymbolAddress((void**)&attn,  g_attn);
    cudaGetSymbolAddress((void**)&proj,  g_proj);

    cudaFuncSetAttribute(gemm_tf32<true>,
                         cudaFuncAttributeMaxDynamicSharedMemorySize, GK_SMEM);
    cudaFuncSetAttribute(gemm_tf32<false>,
                         cudaFuncAttributeMaxDynamicSharedMemorySize, GK_SMEM);
    cudaFuncSetAttribute(flash_tf32,
                         cudaFuncAttributeMaxDynamicSharedMemorySize, FA_SMEM);

    // 1) chunk = windows @ chunk_w^T + chunk_b
    {
        dim3 grid(CD / 128, MROWS / 128);
        gemm_tf32<true><<<grid, 256, GK_SMEM>>>(emb, chunk_w, chunk_b, chunk,
                                                MROWS, CD, 2 * CD);
    }
    // 2) qkv = chunk @ in_proj_w^T + in_proj_b
    {
        dim3 grid(3 * CD / 128, MROWS / 128);
        gemm_tf32<false><<<grid, 256, GK_SMEM>>>(chunk, in_w, in_b, qkv,
                                                 MROWS, 3 * CD, CD);
    }
    // 3) flash attention
    {
        dim3 grid(CS / 128, CB * CH);
        flash_tf32<<<grid, 256, FA_SMEM>>>(qkv, attn);
    }
    // 4) proj = attn @ out_proj_w^T + out_proj_b
    {
        dim3 grid(CD / 128, MROWS / 128);
        gemm_tf32<false><<<grid, 256, GK_SMEM>>>(attn, out_w, out_b, proj,
                                                 MROWS, CD, CD);
    }
    // 5) out = LayerNorm(chunk + proj)
    add_ln<<<MROWS, 256>>>(chunk, proj, ln_g, ln_b, out);
}

// round 7
// speedup vs baseline: 1.2141x; 1.0792x over previous
#include <cuda_runtime.h>
#include <math.h>
#include <stdint.h>

#define CB   4
#define CS   2048
#define CD   1024
#define CH   16
#define CDH  64
#define MROWS (CB*CS)
#define LN_EPS 1e-5f

// ---------------- scratch ----------------
__device__ float g_chunk[(size_t)MROWS*CD];
__device__ float g_qkv  [(size_t)MROWS*3*CD];
__device__ float g_attn [(size_t)MROWS*CD];
__device__ float g_proj [(size_t)MROWS*CD];

// ---------------- helpers ----------------
__device__ __forceinline__ uint32_t f2tf(float x) {
    uint32_t u; asm("cvt.rna.tf32.f32 %0, %1;" : "=r"(u) : "f"(x)); return u;
}
__device__ __forceinline__ float tfbits(float x) {
    return __uint_as_float(f2tf(x));
}
__device__ __forceinline__ float ex2f(float x) {
    float y; asm("ex2.approx.f32 %0, %1;" : "=f"(y) : "f"(x)); return y;
}
__device__ __forceinline__ uint32_t pack_bf16(float lo, float hi) {
    uint32_t r; asm("cvt.rn.bf16x2.f32 %0, %1, %2;" : "=r"(r) : "f"(hi), "f"(lo));
    return r;
}
__device__ __forceinline__ void mma_tf32(float c[4], const uint32_t a[4],
                                         const uint32_t b[2]) {
    asm volatile(
        "mma.sync.aligned.m16n8k8.row.col.f32.tf32.tf32.f32 "
        "{%0,%1,%2,%3}, {%4,%5,%6,%7}, {%8,%9}, {%0,%1,%2,%3};\n"
        : "+f"(c[0]), "+f"(c[1]), "+f"(c[2]), "+f"(c[3])
        : "r"(a[0]), "r"(a[1]), "r"(a[2]), "r"(a[3]), "r"(b[0]), "r"(b[1]));
}
__device__ __forceinline__ void mma_bf16(float c[4], const uint32_t a[4],
                                         const uint32_t b[2]) {
    asm volatile(
        "mma.sync.aligned.m16n8k16.row.col.f32.bf16.bf16.f32 "
        "{%0,%1,%2,%3}, {%4,%5,%6,%7}, {%8,%9}, {%0,%1,%2,%3};\n"
        : "+f"(c[0]), "+f"(c[1]), "+f"(c[2]), "+f"(c[3])
        : "r"(a[0]), "r"(a[1]), "r"(a[2]), "r"(a[3]), "r"(b[0]), "r"(b[1]));
}
__device__ __forceinline__ void ldsm_x4(uint32_t& r0, uint32_t& r1,
                                        uint32_t& r2, uint32_t& r3,
                                        uint32_t addr) {
    asm volatile("ldmatrix.sync.aligned.m8n8.x4.shared.b16 {%0,%1,%2,%3}, [%4];\n"
                 : "=r"(r0), "=r"(r1), "=r"(r2), "=r"(r3) : "r"(addr));
}
__device__ __forceinline__ void ldsm_x4_t(uint32_t& r0, uint32_t& r1,
                                          uint32_t& r2, uint32_t& r3,
                                          uint32_t addr) {
    asm volatile("ldmatrix.sync.aligned.m8n8.x4.trans.shared.b16 {%0,%1,%2,%3}, [%4];\n"
                 : "=r"(r0), "=r"(r1), "=r"(r2), "=r"(r3) : "r"(addr));
}
__device__ __forceinline__ uint32_t smem_u32(const void* p) {
    return (uint32_t)__cvta_generic_to_shared(p);
}
__device__ __forceinline__ void cp16(uint32_t dst, const void* src) {
    asm volatile("cp.async.cg.shared.global [%0], [%1], 16;\n"
                 :: "r"(dst), "l"(src));
}
__device__ __forceinline__ void cp16z(uint32_t dst, const void* src, int srcsz) {
    asm volatile("cp.async.cg.shared.global [%0], [%1], 16, %2;\n"
                 :: "r"(dst), "l"(src), "r"(srcsz));
}
__device__ __forceinline__ void cp_commit() {
    asm volatile("cp.async.commit_group;\n");
}
template<int N> __device__ __forceinline__ void cp_wait() {
    asm volatile("cp.async.wait_group %0;\n" :: "n"(N));
}

// ---------------------------------------------------------------------------
// TF32 NT GEMM, cp.async double-buffered, LDSM fragment loads.
// Operands pass raw fp32 bits to mma.tf32 (truncation).
// 128x128x32 tile, 256 threads, warp tile 64x32.
// ---------------------------------------------------------------------------
#define GK_SMEM (2 * 2 * 128 * 36 * 4)

template<bool WINDOW>
__global__ __launch_bounds__(256, 2)
void gemm_tf32(const float* __restrict__ A, const float* __restrict__ B,
               const float* __restrict__ bias, float* __restrict__ C,
               int M, int N, int K) {
    extern __shared__ float sm[];
    float* As = sm;                 // [2][128][36]
    float* Bs = sm + 2 * 128 * 36;  // [2][128][36]

    int tid = threadIdx.x;
    int bm = blockIdx.y * 128, bn = blockIdx.x * 128;
    int warp = tid >> 5, lane = tid & 31, gid = lane >> 2, tig = lane & 3;
    int l7 = lane & 7, l3 = lane >> 3;
    int wm = (warp >> 2) * 64, wn = (warp & 3) * 32;

    float acc[4][4][4];
#pragma unroll
    for (int i = 0; i < 4; i++)
#pragma unroll
        for (int j = 0; j < 4; j++)
#pragma unroll
            for (int c = 0; c < 4; c++) acc[i][j][c] = 0.f;

    auto load_stage = [&](int st, int k0) {
#pragma unroll
        for (int p = 0; p < 4; p++) {
            int id  = tid + p * 256;
            int row = id >> 3;
            int kq  = (id & 7) << 2;
            uint32_t da = smem_u32(&As[(st * 128 + row) * 36 + kq]);
            if (WINDOW) {
                int m = bm + row;
                int bidx = m >> 11, s = m & (CS - 1);
                int f = k0 + kq, kk = f >> 10, j = f & (CD - 1);
                const float* src = A + (((size_t)bidx * CS + s + kk) << 10) + j;
                cp16z(da, src, (s + kk < CS) ? 16 : 0);
            } else {
                cp16(da, A + (size_t)(bm + row) * K + k0 + kq);
            }
            cp16(smem_u32(&Bs[(st * 128 + row) * 36 + kq]),
                 B + (size_t)(bn + row) * K + k0 + kq);
        }
        cp_commit();
    };

    int nk = K >> 5;
    load_stage(0, 0);
    load_stage(1, 32);

    for (int kc = 0; kc < nk; kc++) {
        int st = kc & 1;
        cp_wait<1>();
        __syncthreads();
        uint32_t Abase = smem_u32(As + st * 128 * 36);
        uint32_t Bbase = smem_u32(Bs + st * 128 * 36);
#pragma unroll
        for (int g = 0; g < 32; g += 8) {
            uint32_t a[4][4], bf[4][2];
#pragma unroll
            for (int ti = 0; ti < 4; ti++) {
                int m0 = wm + ti * 16;
                uint32_t adr = Abase +
                    ((m0 + (l3 & 1) * 8 + l7) * 36 + g + (l3 >> 1) * 4) * 4;
                ldsm_x4(a[ti][0], a[ti][1], a[ti][2], a[ti][3], adr);
            }
#pragma unroll
            for (int tp = 0; tp < 2; tp++) {
                int n0 = wn + tp * 16;
                uint32_t adr = Bbase +
                    ((n0 + (l3 >> 1) * 8 + l7) * 36 + g + (l3 & 1) * 4) * 4;
                ldsm_x4(bf[2 * tp][0], bf[2 * tp][1],
                        bf[2 * tp + 1][0], bf[2 * tp + 1][1], adr);
            }
#pragma unroll
            for (int ti = 0; ti < 4; ti++)
#pragma unroll
                for (int tj = 0; tj < 4; tj++)
                    mma_tf32(acc[ti][tj], a[ti], bf[tj]);
        }
        __syncthreads();
        if (kc + 2 < nk) load_stage(st, (kc + 2) << 5);
        else cp_commit();   // keep wait_group accounting exact
    }

#pragma unroll
    for (int ti = 0; ti < 4; ti++) {
#pragma unroll
        for (int hh = 0; hh < 2; hh++) {
            int row = bm + wm + ti * 16 + gid + 8 * hh;
#pragma unroll
            for (int tj = 0; tj < 4; tj++) {
                int col = bn + wn + tj * 8 + 2 * tig;
                float2 o;
                o.x = acc[ti][tj][2 * hh + 0] + bias[col + 0];
                o.y = acc[ti][tj][2 * hh + 1] + bias[col + 1];
                *(float2*)&C[(size_t)row * N + col] = o;
            }
        }
    }
}

// ---------------------------------------------------------------------------
// Flash attention. 8 warps x 16 q-rows, 256 thr, 2 CTAs/SM.
// kv tiles of 64, cp.async 2-stage. Dedicated bf16 V buffer (no in-place
// overlay). 2 barriers/tile; next-tile load issued before PV.
// S chains split 2x4-deep. Row-sums via ones-column.
// ---------------------------------------------------------------------------
#define FA_KV  (64 * 68)
#define FA_SMEM ((4 * FA_KV) * 4 + 2 * 64 * 36 * 4)   // 88064 B

__global__ __launch_bounds__(256, 2)
void flash_tf32(const float* __restrict__ qkv, float* __restrict__ out) {
    extern __shared__ float sm[];
    float*    Ks   = sm;                      // [2][64][68] f32
    float*    Vraw = sm + 2 * FA_KV;          // [2][64][68] f32
    uint32_t* Vbf  = (uint32_t*)(sm + 4 * FA_KV);  // [2][64][36] bf16x2

    int b = blockIdx.y >> 4, h = blockIdx.y & 15;
    int q0 = blockIdx.x << 7;
    int tid = threadIdx.x, warp = tid >> 5, lane = tid & 31;
    int gid = lane >> 2, tig = lane & 3;
    int wq = warp * 16;
    int l7 = lane & 7, l3 = lane >> 3;

    const size_t rstr = 3 * CD;
    const float* qb = qkv + (size_t)b * CS * rstr + h * CDH;
    const float* kb = qb + CD;
    const float* vb = qb + 2 * CD;
    const float qscale = 1.4426950408889634f * 0.125f;   // log2e / sqrt(dh)

    // ---- stage Q through the K double-buffer (128*68 == 2*FA_KV)
    float* Qt = Ks;
#pragma unroll
    for (int p = 0; p < 8; p++) {
        int id  = tid + p * 256;
        int row = id >> 4;
        int c4  = (id & 15) << 2;
        float4 v = *(const float4*)&qb[(size_t)(q0 + row) * rstr + c4];
        Qt[row * 68 + c4 + 0] = tfbits(v.x * qscale);
        Qt[row * 68 + c4 + 1] = tfbits(v.y * qscale);
        Qt[row * 68 + c4 + 2] = tfbits(v.z * qscale);
        Qt[row * 68 + c4 + 3] = tfbits(v.w * qscale);
    }
    __syncthreads();

    uint32_t qf[8][4];
    {
        int r0 = wq + gid;
#pragma unroll
        for (int g = 0; g < 8; g++) {
            qf[g][0] = __float_as_uint(Qt[r0 * 68 + g * 8 + tig]);
            qf[g][1] = __float_as_uint(Qt[(r0 + 8) * 68 + g * 8 + tig]);
            qf[g][2] = __float_as_uint(Qt[r0 * 68 + g * 8 + tig + 4]);
            qf[g][3] = __float_as_uint(Qt[(r0 + 8) * 68 + g * 8 + tig + 4]);
        }
    }
    __syncthreads();

    auto load_kv = [&](int st, int kt) {
#pragma unroll
        for (int p = 0; p < 4; p++) {
            int id  = tid + p * 256;
            int row = id >> 4;
            int c4  = (id & 15) << 2;
            cp16(smem_u32(&Ks[st * FA_KV + row * 68 + c4]),
                 kb + (size_t)(kt + row) * rstr + c4);
            cp16(smem_u32(&Vraw[st * FA_KV + row * 68 + c4]),
                 vb + (size_t)(kt + row) * rstr + c4);
        }
        cp_commit();
    };

    load_kv(0, 0);
    load_kv(1, 64);

    // O accumulators: 8 d-tiles + 1 ones (row-sum) tile
    float o[9][4];
#pragma unroll
    for (int n = 0; n < 9; n++)
#pragma unroll
        for (int c = 0; c < 4; c++) o[n][c] = 0.f;

    const uint32_t bones = (gid == 0) ? 0x3F803F80u : 0u;
    const int nkt = CS / 64;   // 32

    for (int it = 0; it < nkt; it++) {
        int st = it & 1;
        cp_wait<1>();
        __syncthreads();
        uint32_t Kbase = smem_u32(Ks + st * FA_KV);
        const float* Vr = Vraw + st * FA_KV;
        uint32_t* Vw = Vbf + st * 64 * 36;
        uint32_t Vbase = smem_u32(Vw);

        // ---- V convert: raw f32 -> dedicated bf16 buffer (no hazard)
#pragma unroll
        for (int p = 0; p < 4; p++) {
            int id  = tid + p * 256;
            int row = id >> 4;
            int c4  = (id & 15) << 2;
            float4 v = *(const float4*)&Vr[row * 68 + c4];
            uint2 w;
            w.x = pack_bf16(v.x, v.y);
            w.y = pack_bf16(v.z, v.w);
            *(uint2*)&Vw[row * 36 + (c4 >> 1)] = w;
        }

        // ---- S = Q @ K^T per n-pair; split 2x4-deep chains; exp -> pf
        uint32_t pf[4][4];
#pragma unroll
        for (int np = 0; np < 4; np++) {
            float sc[2][2][4];
#pragma unroll
            for (int nn = 0; nn < 2; nn++)
#pragma unroll
                for (int hf = 0; hf < 2; hf++)
#pragma unroll
                    for (int c = 0; c < 4; c++) sc[nn][hf][c] = 0.f;
#pragma unroll
            for (int j = 0; j < 4; j++) {
#pragma unroll
                for (int nn = 0; nn < 2; nn++) {
                    uint32_t adr = Kbase +
                        ((np * 16 + nn * 8 + l7) * 68 + l3 * 4) * 4 + j * 64;
                    uint32_t k0, k1, k2, k3;
                    ldsm_x4(k0, k1, k2, k3, adr);
                    uint32_t b0[2] = {k0, k1};
                    uint32_t b1[2] = {k2, k3};
                    mma_tf32(sc[nn][j >> 1], qf[2 * j], b0);
                    mma_tf32(sc[nn][j >> 1], qf[2 * j + 1], b1);
                }
            }
#pragma unroll
            for (int nn = 0; nn < 2; nn++) {
                float s0 = sc[nn][0][0] + sc[nn][1][0];
                float s1 = sc[nn][0][1] + sc[nn][1][1];
                float s2 = sc[nn][0][2] + sc[nn][1][2];
                float s3 = sc[nn][0][3] + sc[nn][1][3];
                pf[np][nn * 2 + 0] = pack_bf16(ex2f(s0), ex2f(s1));
                pf[np][nn * 2 + 1] = pack_bf16(ex2f(s2), ex2f(s3));
            }
        }

        __syncthreads();   // Vbf visible; K[st]/Vraw[st] fully consumed

        // refill raw buffers for tile it+2 while PV runs
        if (it + 2 < nkt) load_kv(st, (it + 2) * 64);
        else cp_commit();

        // ---- O += P @ V via ldmatrix.trans on bf16 V
#pragma unroll
        for (int t = 0; t < 4; t++) {
#pragma unroll
            for (int a = 0; a < 4; a++) {
                uint32_t adr = Vbase +
                    (16 * t + (l3 & 1) * 8 + l7) * 144 +
                    (2 * a + (l3 >> 1)) * 16;
                uint32_t v0, v1, v2, v3;
                ldsm_x4_t(v0, v1, v2, v3, adr);
                uint32_t bv0[2] = {v0, v1};
                uint32_t bv1[2] = {v2, v3};
                mma_bf16(o[2 * a],     pf[t], bv0);
                mma_bf16(o[2 * a + 1], pf[t], bv1);
            }
            {
                uint32_t bv[2] = {bones, bones};
                mma_bf16(o[8], pf[t], bv);
            }
        }
    }

    // normalize + write (row sums in tig==0 lanes of o[8])
    int base = lane & 28;
#pragma unroll
    for (int hh = 0; hh < 2; hh++) {
        float lsv = __shfl_sync(0xffffffffu, o[8][hh ? 2 : 0], base);
        float inv = 1.f / lsv;
        int row = q0 + wq + gid + 8 * hh;
#pragma unroll
        for (int n = 0; n < 8; n++) {
            int col = h * CDH + n * 8 + 2 * tig;
            float2 ov = make_float2(o[n][2 * hh] * inv,
                                    o[n][2 * hh + 1] * inv);
            *(float2*)&out[((size_t)b * CS + row) * CD + col] = ov;
        }
    }
}

// ---------------------------------------------------------------------------
// Fused residual add + LayerNorm
// ---------------------------------------------------------------------------
__global__ __launch_bounds__(256)
void add_ln(const float* __restrict__ chunk, const float* __restrict__ proj,
            const float* __restrict__ g, const float* __restrict__ beta,
            float* __restrict__ out) {
    int row = blockIdx.x;
    int tid = threadIdx.x;
    size_t base = (size_t)row * CD + tid * 4;

    float4 c = *(const float4*)&chunk[base];
    float4 p = *(const float4*)&proj[base];
    float4 x = make_float4(c.x + p.x, c.y + p.y, c.z + p.z, c.w + p.w);

    float s  = x.x + x.y + x.z + x.w;
    float s2 = x.x * x.x + x.y * x.y + x.z * x.z + x.w * x.w;
#pragma unroll
    for (int off = 16; off; off >>= 1) {
        s  += __shfl_xor_sync(0xffffffffu, s,  off);
        s2 += __shfl_xor_sync(0xffffffffu, s2, off);
    }
    __shared__ float rs[8], rs2[8];
    __shared__ float s_mu, s_rstd;
    int lane = tid & 31, warp = tid >> 5;
    if (lane == 0) { rs[warp] = s; rs2[warp] = s2; }
    __syncthreads();
    if (tid == 0) {
        float a = 0.f, b2 = 0.f;
#pragma unroll
        for (int w = 0; w < 8; w++) { a += rs[w]; b2 += rs2[w]; }
        float mean = a * (1.f / CD);
        float var  = b2 * (1.f / CD) - mean * mean;
        s_mu = mean;
        s_rstd = rsqrtf(var + LN_EPS);
    }
    __syncthreads();
    float mu = s_mu, rstd = s_rstd;

    float4 gv = *(const float4*)&g[tid * 4];
    float4 bv = *(const float4*)&beta[tid * 4];
    float4 y;
    y.x = (x.x - mu) * rstd * gv.x + bv.x;
    y.y = (x.y - mu) * rstd * gv.y + bv.y;
    y.z = (x.z - mu) * rstd * gv.z + bv.z;
    y.w = (x.w - mu) * rstd * gv.w + bv.w;
    *(float4*)&out[base] = y;
}

// ---------------------------------------------------------------------------
extern "C" void kernel_launch(void* const* d_in, const int* in_sizes, int n_in,
                              void* d_out, int out_size) {
    const float* emb     = (const float*)d_in[0];
    const float* chunk_w = (const float*)d_in[1];
    const float* chunk_b = (const float*)d_in[2];
    const float* in_w    = (const float*)d_in[3];
    const float* in_b    = (const float*)d_in[4];
    const float* out_w   = (const float*)d_in[5];
    const float* out_b   = (const float*)d_in[6];
    const float* ln_g    = (const float*)d_in[7];
    const float* ln_b    = (const float*)d_in[8];
    float* out = (float*)d_out;

    float *chunk, *qkv, *attn, *proj;
    cudaGetSymbolAddress((void**)&chunk, g_chunk);
    cudaGetSymbolAddress((void**)&qkv,   g_qkv);
    cudaGetSymbolAddress((void**)&attn,  g_attn);
    cudaGetSymbolAddress((void**)&proj,  g_proj);

    cudaFuncSetAttribute(gemm_tf32<true>,
                         cudaFuncAttributeMaxDynamicSharedMemorySize, GK_SMEM);
    cudaFuncSetAttribute(gemm_tf32<false>,
                         cudaFuncAttributeMaxDynamicSharedMemorySize, GK_SMEM);
    cudaFuncSetAttribute(flash_tf32,
                         cudaFuncAttributeMaxDynamicSharedMemorySize, FA_SMEM);

    // 1) chunk = windows @ chunk_w^T + chunk_b
    {
        dim3 grid(CD / 128, MROWS / 128);
        gemm_tf32<true><<<grid, 256, GK_SMEM>>>(emb, chunk_w, chunk_b, chunk,
                                                MROWS, CD, 2 * CD);
    }
    // 2) qkv = chunk @ in_proj_w^T + in_proj_b
    {
        dim3 grid(3 * CD / 128, MROWS / 128);
        gemm_tf32<false><<<grid, 256, GK_SMEM>>>(chunk, in_w, in_b, qkv,
                                                 MROWS, 3 * CD, CD);
    }
    // 3) flash attention
    {
        dim3 grid(CS / 128, CB * CH);
        flash_tf32<<<grid, 256, FA_SMEM>>>(qkv, attn);
    }
    // 4) proj = attn @ out_proj_w^T + out_proj_b
    {
        dim3 grid(CD / 128, MROWS / 128);
        gemm_tf32<false><<<grid, 256, GK_SMEM>>>(attn, out_w, out_b, proj,
                                                 MROWS, CD, CD);
    }
    // 5) out = LayerNorm(chunk + proj)
    add_ln<<<MROWS, 256>>>(chunk, proj, ln_g, ln_b, out);
}

// round 8
// speedup vs baseline: 1.2553x; 1.0339x over previous
#include <cuda_runtime.h>
#include <math.h>
#include <stdint.h>

#define CB   4
#define CS   2048
#define CD   1024
#define CH   16
#define CDH  64
#define MROWS (CB*CS)
#define LN_EPS 1e-5f

// ---------------- scratch ----------------
__device__ float g_chunk[(size_t)MROWS*CD];
__device__ float g_qkv  [(size_t)MROWS*3*CD];
__device__ float g_attn [(size_t)MROWS*CD];
__device__ float g_proj [(size_t)MROWS*CD];

// ---------------- helpers ----------------
__device__ __forceinline__ uint32_t f2tf(float x) {
    uint32_t u; asm("cvt.rna.tf32.f32 %0, %1;" : "=r"(u) : "f"(x)); return u;
}
__device__ __forceinline__ float tfbits(float x) {
    return __uint_as_float(f2tf(x));
}
__device__ __forceinline__ float ex2f(float x) {
    float y; asm("ex2.approx.f32 %0, %1;" : "=f"(y) : "f"(x)); return y;
}
__device__ __forceinline__ uint32_t pack_bf16(float lo, float hi) {
    uint32_t r; asm("cvt.rn.bf16x2.f32 %0, %1, %2;" : "=r"(r) : "f"(hi), "f"(lo));
    return r;
}
__device__ __forceinline__ void mma_tf32(float c[4], const uint32_t a[4],
                                         const uint32_t b[2]) {
    asm volatile(
        "mma.sync.aligned.m16n8k8.row.col.f32.tf32.tf32.f32 "
        "{%0,%1,%2,%3}, {%4,%5,%6,%7}, {%8,%9}, {%0,%1,%2,%3};\n"
        : "+f"(c[0]), "+f"(c[1]), "+f"(c[2]), "+f"(c[3])
        : "r"(a[0]), "r"(a[1]), "r"(a[2]), "r"(a[3]), "r"(b[0]), "r"(b[1]));
}
__device__ __forceinline__ void mma_bf16(float c[4], const uint32_t a[4],
                                         const uint32_t b[2]) {
    asm volatile(
        "mma.sync.aligned.m16n8k16.row.col.f32.bf16.bf16.f32 "
        "{%0,%1,%2,%3}, {%4,%5,%6,%7}, {%8,%9}, {%0,%1,%2,%3};\n"
        : "+f"(c[0]), "+f"(c[1]), "+f"(c[2]), "+f"(c[3])
        : "r"(a[0]), "r"(a[1]), "r"(a[2]), "r"(a[3]), "r"(b[0]), "r"(b[1]));
}
__device__ __forceinline__ void ldsm_x4(uint32_t& r0, uint32_t& r1,
                                        uint32_t& r2, uint32_t& r3,
                                        uint32_t addr) {
    asm volatile("ldmatrix.sync.aligned.m8n8.x4.shared.b16 {%0,%1,%2,%3}, [%4];\n"
                 : "=r"(r0), "=r"(r1), "=r"(r2), "=r"(r3) : "r"(addr));
}
__device__ __forceinline__ void ldsm_x4_t(uint32_t& r0, uint32_t& r1,
                                          uint32_t& r2, uint32_t& r3,
                                          uint32_t addr) {
    asm volatile("ldmatrix.sync.aligned.m8n8.x4.trans.shared.b16 {%0,%1,%2,%3}, [%4];\n"
                 : "=r"(r0), "=r"(r1), "=r"(r2), "=r"(r3) : "r"(addr));
}
__device__ __forceinline__ uint32_t smem_u32(const void* p) {
    return (uint32_t)__cvta_generic_to_shared(p);
}
__device__ __forceinline__ void cp16(uint32_t dst, const void* src) {
    asm volatile("cp.async.cg.shared.global [%0], [%1], 16;\n"
                 :: "r"(dst), "l"(src));
}
__device__ __forceinline__ void cp16z(uint32_t dst, const void* src, int srcsz) {
    asm volatile("cp.async.cg.shared.global [%0], [%1], 16, %2;\n"
                 :: "r"(dst), "l"(src), "r"(srcsz));
}
__device__ __forceinline__ void cp_commit() {
    asm volatile("cp.async.commit_group;\n");
}
template<int N> __device__ __forceinline__ void cp_wait() {
    asm volatile("cp.async.wait_group %0;\n" :: "n"(N));
}

// ---------------------------------------------------------------------------
// TF32 NT GEMM, 3-stage cp.async pipeline, ONE sync per k32 iteration.
// LDSM fragment loads; raw fp32 bits into mma.tf32 (truncation).
// 128x128x32 tile, 256 threads, warp tile 64x32.
// ---------------------------------------------------------------------------
#define GSTG (128 * 36)
#define GK_SMEM (3 * 2 * GSTG * 4)   // 110592 B

template<bool WINDOW>
__global__ __launch_bounds__(256, 2)
void gemm_tf32(const float* __restrict__ A, const float* __restrict__ B,
               const float* __restrict__ bias, float* __restrict__ C,
               int M, int N, int K) {
    extern __shared__ float sm[];
    float* As = sm;               // [3][128][36]
    float* Bs = sm + 3 * GSTG;    // [3][128][36]

    int tid = threadIdx.x;
    int bm = blockIdx.y * 128, bn = blockIdx.x * 128;
    int warp = tid >> 5, lane = tid & 31, gid = lane >> 2, tig = lane & 3;
    int l7 = lane & 7, l3 = lane >> 3;
    int wm = (warp >> 2) * 64, wn = (warp & 3) * 32;

    float acc[4][4][4];
#pragma unroll
    for (int i = 0; i < 4; i++)
#pragma unroll
        for (int j = 0; j < 4; j++)
#pragma unroll
            for (int c = 0; c < 4; c++) acc[i][j][c] = 0.f;

    auto load_stage = [&](int st, int k0) {
#pragma unroll
        for (int p = 0; p < 4; p++) {
            int id  = tid + p * 256;
            int row = id >> 3;
            int kq  = (id & 7) << 2;
            uint32_t da = smem_u32(&As[st * GSTG + row * 36 + kq]);
            if (WINDOW) {
                int m = bm + row;
                int bidx = m >> 11, s = m & (CS - 1);
                int f = k0 + kq, kk = f >> 10, j = f & (CD - 1);
                const float* src = A + (((size_t)bidx * CS + s + kk) << 10) + j;
                cp16z(da, src, (s + kk < CS) ? 16 : 0);
            } else {
                cp16(da, A + (size_t)(bm + row) * K + k0 + kq);
            }
            cp16(smem_u32(&Bs[st * GSTG + row * 36 + kq]),
                 B + (size_t)(bn + row) * K + k0 + kq);
        }
        cp_commit();
    };

    int nk = K >> 5;   // >= 3 for all our shapes
    load_stage(0, 0);
    load_stage(1, 32);

    int st = 0;        // stage being consumed this iteration
    int pfst = 2;      // stage the prefetch targets: (kc+2) % 3
    for (int kc = 0; kc < nk; kc++) {
        cp_wait<1>();       // stage kc landed (kc+1 still in flight)
        __syncthreads();    // everyone done reading stage (kc-1) == pfst

        int pf = kc + 2;
        if (pf < nk) load_stage(pfst, pf << 5);
        else cp_commit();   // keep group accounting exact

        uint32_t Abase = smem_u32(As + st * GSTG);
        uint32_t Bbase = smem_u32(Bs + st * GSTG);
#pragma unroll
        for (int g = 0; g < 32; g += 8) {
            uint32_t a[4][4], bf[4][2];
#pragma unroll
            for (int ti = 0; ti < 4; ti++) {
                int m0 = wm + ti * 16;
                uint32_t adr = Abase +
                    ((m0 + (l3 & 1) * 8 + l7) * 36 + g + (l3 >> 1) * 4) * 4;
                ldsm_x4(a[ti][0], a[ti][1], a[ti][2], a[ti][3], adr);
            }
#pragma unroll
            for (int tp = 0; tp < 2; tp++) {
                int n0 = wn + tp * 16;
                uint32_t adr = Bbase +
                    ((n0 + (l3 >> 1) * 8 + l7) * 36 + g + (l3 & 1) * 4) * 4;
                ldsm_x4(bf[2 * tp][0], bf[2 * tp][1],
                        bf[2 * tp + 1][0], bf[2 * tp + 1][1], adr);
            }
#pragma unroll
            for (int ti = 0; ti < 4; ti++)
#pragma unroll
                for (int tj = 0; tj < 4; tj++)
                    mma_tf32(acc[ti][tj], a[ti], bf[tj]);
        }

        st   = (st   == 2) ? 0 : st + 1;
        pfst = (pfst == 2) ? 0 : pfst + 1;
    }

#pragma unroll
    for (int ti = 0; ti < 4; ti++) {
#pragma unroll
        for (int hh = 0; hh < 2; hh++) {
            int row = bm + wm + ti * 16 + gid + 8 * hh;
#pragma unroll
            for (int tj = 0; tj < 4; tj++) {
                int col = bn + wn + tj * 8 + 2 * tig;
                float2 o;
                o.x = acc[ti][tj][2 * hh + 0] + bias[col + 0];
                o.y = acc[ti][tj][2 * hh + 1] + bias[col + 1];
                *(float2*)&C[(size_t)row * N + col] = o;
            }
        }
    }
}

// ---------------------------------------------------------------------------
// Flash attention (unchanged from R7). 8 warps x 16 q-rows, 2 CTAs/SM.
// ---------------------------------------------------------------------------
#define FA_KV  (64 * 68)
#define FA_SMEM ((4 * FA_KV) * 4 + 2 * 64 * 36 * 4)   // 88064 B

__global__ __launch_bounds__(256, 2)
void flash_tf32(const float* __restrict__ qkv, float* __restrict__ out) {
    extern __shared__ float sm[];
    float*    Ks   = sm;                      // [2][64][68] f32
    float*    Vraw = sm + 2 * FA_KV;          // [2][64][68] f32
    uint32_t* Vbf  = (uint32_t*)(sm + 4 * FA_KV);  // [2][64][36] bf16x2

    int b = blockIdx.y >> 4, h = blockIdx.y & 15;
    int q0 = blockIdx.x << 7;
    int tid = threadIdx.x, warp = tid >> 5, lane = tid & 31;
    int gid = lane >> 2, tig = lane & 3;
    int wq = warp * 16;
    int l7 = lane & 7, l3 = lane >> 3;

    const size_t rstr = 3 * CD;
    const float* qb = qkv + (size_t)b * CS * rstr + h * CDH;
    const float* kb = qb + CD;
    const float* vb = qb + 2 * CD;
    const float qscale = 1.4426950408889634f * 0.125f;   // log2e / sqrt(dh)

    // ---- stage Q through the K double-buffer (128*68 == 2*FA_KV)
    float* Qt = Ks;
#pragma unroll
    for (int p = 0; p < 8; p++) {
        int id  = tid + p * 256;
        int row = id >> 4;
        int c4  = (id & 15) << 2;
        float4 v = *(const float4*)&qb[(size_t)(q0 + row) * rstr + c4];
        Qt[row * 68 + c4 + 0] = tfbits(v.x * qscale);
        Qt[row * 68 + c4 + 1] = tfbits(v.y * qscale);
        Qt[row * 68 + c4 + 2] = tfbits(v.z * qscale);
        Qt[row * 68 + c4 + 3] = tfbits(v.w * qscale);
    }
    __syncthreads();

    uint32_t qf[8][4];
    {
        int r0 = wq + gid;
#pragma unroll
        for (int g = 0; g < 8; g++) {
            qf[g][0] = __float_as_uint(Qt[r0 * 68 + g * 8 + tig]);
            qf[g][1] = __float_as_uint(Qt[(r0 + 8) * 68 + g * 8 + tig]);
            qf[g][2] = __float_as_uint(Qt[r0 * 68 + g * 8 + tig + 4]);
            qf[g][3] = __float_as_uint(Qt[(r0 + 8) * 68 + g * 8 + tig + 4]);
        }
    }
    __syncthreads();

    auto load_kv = [&](int st, int kt) {
#pragma unroll
        for (int p = 0; p < 4; p++) {
            int id  = tid + p * 256;
            int row = id >> 4;
            int c4  = (id & 15) << 2;
            cp16(smem_u32(&Ks[st * FA_KV + row * 68 + c4]),
                 kb + (size_t)(kt + row) * rstr + c4);
            cp16(smem_u32(&Vraw[st * FA_KV + row * 68 + c4]),
                 vb + (size_t)(kt + row) * rstr + c4);
        }
        cp_commit();
    };

    load_kv(0, 0);
    load_kv(1, 64);

    float o[9][4];
#pragma unroll
    for (int n = 0; n < 9; n++)
#pragma unroll
        for (int c = 0; c < 4; c++) o[n][c] = 0.f;

    const uint32_t bones = (gid == 0) ? 0x3F803F80u : 0u;
    const int nkt = CS / 64;   // 32

    for (int it = 0; it < nkt; it++) {
        int st = it & 1;
        cp_wait<1>();
        __syncthreads();
        uint32_t Kbase = smem_u32(Ks + st * FA_KV);
        const float* Vr = Vraw + st * FA_KV;
        uint32_t* Vw = Vbf + st * 64 * 36;
        uint32_t Vbase = smem_u32(Vw);

        // V convert: raw f32 -> dedicated bf16 buffer
#pragma unroll
        for (int p = 0; p < 4; p++) {
            int id  = tid + p * 256;
            int row = id >> 4;
            int c4  = (id & 15) << 2;
            float4 v = *(const float4*)&Vr[row * 68 + c4];
            uint2 w;
            w.x = pack_bf16(v.x, v.y);
            w.y = pack_bf16(v.z, v.w);
            *(uint2*)&Vw[row * 36 + (c4 >> 1)] = w;
        }

        // S = Q @ K^T per n-pair; split 2x4-deep chains; exp -> pf
        uint32_t pf[4][4];
#pragma unroll
        for (int np = 0; np < 4; np++) {
            float sc[2][2][4];
#pragma unroll
            for (int nn = 0; nn < 2; nn++)
#pragma unroll
                for (int hf = 0; hf < 2; hf++)
#pragma unroll
                    for (int c = 0; c < 4; c++) sc[nn][hf][c] = 0.f;
#pragma unroll
            for (int j = 0; j < 4; j++) {
#pragma unroll
                for (int nn = 0; nn < 2; nn++) {
                    uint32_t adr = Kbase +
                        ((np * 16 + nn * 8 + l7) * 68 + l3 * 4) * 4 + j * 64;
                    uint32_t k0, k1, k2, k3;
                    ldsm_x4(k0, k1, k2, k3, adr);
                    uint32_t b0[2] = {k0, k1};
                    uint32_t b1[2] = {k2, k3};
                    mma_tf32(sc[nn][j >> 1], qf[2 * j], b0);
                    mma_tf32(sc[nn][j >> 1], qf[2 * j + 1], b1);
                }
            }
#pragma unroll
            for (int nn = 0; nn < 2; nn++) {
                float s0 = sc[nn][0][0] + sc[nn][1][0];
                float s1 = sc[nn][0][1] + sc[nn][1][1];
                float s2 = sc[nn][0][2] + sc[nn][1][2];
                float s3 = sc[nn][0][3] + sc[nn][1][3];
                pf[np][nn * 2 + 0] = pack_bf16(ex2f(s0), ex2f(s1));
                pf[np][nn * 2 + 1] = pack_bf16(ex2f(s2), ex2f(s3));
            }
        }

        __syncthreads();   // Vbf visible; K[st]/Vraw[st] fully consumed

        if (it + 2 < nkt) load_kv(st, (it + 2) * 64);
        else cp_commit();

        // O += P @ V via ldmatrix.trans on bf16 V
#pragma unroll
        for (int t = 0; t < 4; t++) {
#pragma unroll
            for (int a = 0; a < 4; a++) {
                uint32_t adr = Vbase +
                    (16 * t + (l3 & 1) * 8 + l7) * 144 +
                    (2 * a + (l3 >> 1)) * 16;
                uint32_t v0, v1, v2, v3;
                ldsm_x4_t(v0, v1, v2, v3, adr);
                uint32_t bv0[2] = {v0, v1};
                uint32_t bv1[2] = {v2, v3};
                mma_bf16(o[2 * a],     pf[t], bv0);
                mma_bf16(o[2 * a + 1], pf[t], bv1);
            }
            {
                uint32_t bv[2] = {bones, bones};
                mma_bf16(o[8], pf[t], bv);
            }
        }
    }

    int base = lane & 28;
#pragma unroll
    for (int hh = 0; hh < 2; hh++) {
        float lsv = __shfl_sync(0xffffffffu, o[8][hh ? 2 : 0], base);
        float inv = 1.f / lsv;
        int row = q0 + wq + gid + 8 * hh;
#pragma unroll
        for (int n = 0; n < 8; n++) {
            int col = h * CDH + n * 8 + 2 * tig;
            float2 ov = make_float2(o[n][2 * hh] * inv,
                                    o[n][2 * hh + 1] * inv);
            *(float2*)&out[((size_t)b * CS + row) * CD + col] = ov;
        }
    }
}

// ---------------------------------------------------------------------------
// Fused residual add + LayerNorm
// ---------------------------------------------------------------------------
__global__ __launch_bounds__(256)
void add_ln(const float* __restrict__ chunk, const float* __restrict__ proj,
            const float* __restrict__ g, const float* __restrict__ beta,
            float* __restrict__ out) {
    int row = blockIdx.x;
    int tid = threadIdx.x;
    size_t base = (size_t)row * CD + tid * 4;

    float4 c = *(const float4*)&chunk[base];
    float4 p = *(const float4*)&proj[base];
    float4 x = make_float4(c.x + p.x, c.y + p.y, c.z + p.z, c.w + p.w);

    float s  = x.x + x.y + x.z + x.w;
    float s2 = x.x * x.x + x.y * x.y + x.z * x.z + x.w * x.w;
#pragma unroll
    for (int off = 16; off; off >>= 1) {
        s  += __shfl_xor_sync(0xffffffffu, s,  off);
        s2 += __shfl_xor_sync(0xffffffffu, s2, off);
    }
    __shared__ float rs[8], rs2[8];
    __shared__ float s_mu, s_rstd;
    int lane = tid & 31, warp = tid >> 5;
    if (lane == 0) { rs[warp] = s; rs2[warp] = s2; }
    __syncthreads();
    if (tid == 0) {
        float a = 0.f, b2 = 0.f;
#pragma unroll
        for (int w = 0; w < 8; w++) { a += rs[w]; b2 += rs2[w]; }
        float mean = a * (1.f / CD);
        float var  = b2 * (1.f / CD) - mean * mean;
        s_mu = mean;
        s_rstd = rsqrtf(var + LN_EPS);
    }
    __syncthreads();
    float mu = s_mu, rstd = s_rstd;

    float4 gv = *(const float4*)&g[tid * 4];
    float4 bv = *(const float4*)&beta[tid * 4];
    float4 y;
    y.x = (x.x - mu) * rstd * gv.x + bv.x;
    y.y = (x.y - mu) * rstd * gv.y + bv.y;
    y.z = (x.z - mu) * rstd * gv.z + bv.z;
    y.w = (x.w - mu) * rstd * gv.w + bv.w;
    *(float4*)&out[base] = y;
}

// ---------------------------------------------------------------------------
extern "C" void kernel_launch(void* const* d_in, const int* in_sizes, int n_in,
                              void* d_out, int out_size) {
    const float* emb     = (const float*)d_in[0];
    const float* chunk_w = (const float*)d_in[1];
    const float* chunk_b = (const float*)d_in[2];
    const float* in_w    = (const float*)d_in[3];
    const float* in_b    = (const float*)d_in[4];
    const float* out_w   = (const float*)d_in[5];
    const float* out_b   = (const float*)d_in[6];
    const float* ln_g    = (const float*)d_in[7];
    const float* ln_b    = (const float*)d_in[8];
    float* out = (float*)d_out;

    float *chunk, *qkv, *attn, *proj;
    cudaGetSymbolAddress((void**)&chunk, g_chunk);
    cudaGetSymbolAddress((void**)&qkv,   g_qkv);
    cudaGetSymbolAddress((void**)&attn,  g_attn);
    cudaGetSymbolAddress((void**)&proj,  g_proj);

    cudaFuncSetAttribute(gemm_tf32<true>,
                         cudaFuncAttributeMaxDynamicSharedMemorySize, GK_SMEM);
    cudaFuncSetAttribute(gemm_tf32<false>,
                         cudaFuncAttributeMaxDynamicSharedMemorySize, GK_SMEM);
    cudaFuncSetAttribute(flash_tf32,
                         cudaFuncAttributeMaxDynamicSharedMemorySize, FA_SMEM);

    // 1) chunk = windows @ chunk_w^T + chunk_b
    {
        dim3 grid(CD / 128, MROWS / 128);
        gemm_tf32<true><<<grid, 256, GK_SMEM>>>(emb, chunk_w, chunk_b, chunk,
                                                MROWS, CD, 2 * CD);
    }
    // 2) qkv = chunk @ in_proj_w^T + in_proj_b
    {
        dim3 grid(3 * CD / 128, MROWS / 128);
        gemm_tf32<false><<<grid, 256, GK_SMEM>>>(chunk, in_w, in_b, qkv,
                                                 MROWS, 3 * CD, CD);
    }
    // 3) flash attention
    {
        dim3 grid(CS / 128, CB * CH);
        flash_tf32<<<grid, 256, FA_SMEM>>>(qkv, attn);
    }
    // 4) proj = attn @ out_proj_w^T + out_proj_b
    {
        dim3 grid(CD / 128, MROWS / 128);
        gemm_tf32<false><<<grid, 256, GK_SMEM>>>(attn, out_w, out_b, proj,
                                                 MROWS, CD, CD);
    }
    // 5) out = LayerNorm(chunk + proj)
    add_ln<<<MROWS, 256>>>(chunk, proj, ln_g, ln_b, out);
}